// round 11
// baseline (speedup 1.0000x reference)
#include <cuda_runtime.h>
typedef unsigned int u32;

#define Nn 65536
#define NK (Nn*16)
#define NTILES (Nn/8)
#define NT 512
#define GRID_MAIN 148

// ---- k_main float offsets in dynamic smem ----
#define F_ACT   0          // 128 x 132 A-tile (h, then px)
#define F_A1H   16896
#define F_A1L   18432
#define F_W1FH  19968
#define F_W1FL  20992
#define F_W2F   22016      // w2 frags
#define F_WSF   30208      // ws frags
#define F_PSM   46592      // 8 x 48
#define F_B2    46976
#define F_TOTAL 47040
#define SMEM_BYTES (F_TOTAL*4)

// ---- k_out float offsets ----
#define O_WOF 0            // 16K x 8n x 32 x 2 = 8192 floats
#define O_BO  8192
#define O_BNS 8256
#define O_BNQ 8320
#define O_FT  8384         // 128 x 132
#define O_TOTAL 25280
#define OSMEM_BYTES (O_TOTAL*4)
#define ONT 256

__device__ __forceinline__ float to_tf32(float x){
    float r; asm("cvt.rna.tf32.f32 %0, %1;":"=f"(r):"f"(x)); return r;
}
__device__ __forceinline__ void mma4(float* d, u32 a0, u32 a1, u32 a2, u32 a3,
                                     u32 b0, u32 b1){
    asm volatile("mma.sync.aligned.m16n8k8.row.col.f32.tf32.tf32.f32 "
        "{%0,%1,%2,%3}, {%4,%5,%6,%7}, {%8,%9}, {%0,%1,%2,%3};"
        : "+f"(d[0]),"+f"(d[1]),"+f"(d[2]),"+f"(d[3])
        : "r"(a0),"r"(a1),"r"(a2),"r"(a3),"r"(b0),"r"(b1));
}

// ---- scratch globals ----
__device__ float g_M1[10], g_M2[55], g_w1p[1280], g_c1[128];
__device__ float g_sum2[64], g_sumsq2[64], g_a2[64], g_c2[64];
__device__ float g_feat[(size_t)Nn*128];     // 32 MB pooled features

__global__ void k_zero(){
    int t = threadIdx.x;
    if (t < 10) g_M1[t]=0.f;
    if (t < 55) g_M2[t]=0.f;
    if (t < 64){ g_sum2[t]=0.f; g_sumsq2[t]=0.f; }
}

// ---- K1: concat moments, center-factored ----
__global__ void k_stats(const float* __restrict__ p){
    __shared__ float red[8][65];
    float m1[10], m2[55];
#pragma unroll
    for (int i=0;i<10;i++) m1[i]=0.f;
#pragma unroll
    for (int i=0;i<55;i++) m2[i]=0.f;

    int n = blockIdx.x*blockDim.x + threadIdx.x;
    {
        float4 pr[12];
        const float4* pp = (const float4*)(p + (size_t)n*48);
#pragma unroll
        for (int i=0;i<12;i++) pr[i] = pp[i];
        const float* pc = (const float*)pr;
        float C0=pc[0], C1=pc[1], C2=pc[2];
        float Sq0=0.f,Sq1=0.f,Sq2=0.f;
        float Q00=0.f,Q01=0.f,Q02=0.f,Q11=0.f,Q12=0.f,Q22=0.f;
        float Sd=0.f, Sdq0=0.f,Sdq1=0.f,Sdq2=0.f, Sdd=0.f;
#pragma unroll
        for (int k=0;k<16;k++){
            float qx=pc[3*k], qy=pc[3*k+1], qz=pc[3*k+2];
            float dx=C0-qx, dy=C1-qy, dz=C2-qz;
            float d2 = dx*dx + dy*dy + dz*dz;
            float ds = sqrtf(d2);
            Sq0+=qx; Sq1+=qy; Sq2+=qz;
            Q00=fmaf(qx,qx,Q00); Q01=fmaf(qx,qy,Q01); Q02=fmaf(qx,qz,Q02);
            Q11=fmaf(qy,qy,Q11); Q12=fmaf(qy,qz,Q12); Q22=fmaf(qz,qz,Q22);
            Sd+=ds; Sdq0=fmaf(ds,qx,Sdq0); Sdq1=fmaf(ds,qy,Sdq1); Sdq2=fmaf(ds,qz,Sdq2);
            Sdd+=d2;
        }
        float C[3]={C0,C1,C2};
        float Sq[3]={Sq0,Sq1,Sq2};
        float QQ[3][3]={{Q00,Q01,Q02},{Q01,Q11,Q12},{Q02,Q12,Q22}};
        float SDQ[3]={Sdq0,Sdq1,Sdq2};
#pragma unroll
        for (int i=0;i<3;i++){
            m1[i]   += 16.f*C[i];
            m1[3+i] += Sq[i];
            m1[6+i] += 16.f*C[i]-Sq[i];
        }
        m1[9] += Sd;
        int t = 0;
#pragma unroll
        for (int a=0;a<3;a++){
#pragma unroll
            for (int b=a;b<3;b++) m2[t++] += 16.f*C[a]*C[b];
#pragma unroll
            for (int b=0;b<3;b++) m2[t++] += C[a]*Sq[b];
#pragma unroll
            for (int b=0;b<3;b++) m2[t++] += C[a]*(16.f*C[b]-Sq[b]);
            m2[t++] += C[a]*Sd;
        }
#pragma unroll
        for (int a=0;a<3;a++){
#pragma unroll
            for (int b=a;b<3;b++) m2[t++] += QQ[a][b];
#pragma unroll
            for (int b=0;b<3;b++) m2[t++] += C[b]*Sq[a]-QQ[a][b];
            m2[t++] += SDQ[a];
        }
#pragma unroll
        for (int a=0;a<3;a++){
#pragma unroll
            for (int b=a;b<3;b++)
                m2[t++] += 16.f*C[a]*C[b]-C[a]*Sq[b]-C[b]*Sq[a]+QQ[a][b];
            m2[t++] += C[a]*Sd - SDQ[a];
        }
        m2[t++] += Sdd;
    }
#pragma unroll
    for (int off=16; off>0; off>>=1){
#pragma unroll
        for (int i=0;i<10;i++) m1[i] += __shfl_down_sync(0xffffffffu, m1[i], off);
#pragma unroll
        for (int i=0;i<55;i++) m2[i] += __shfl_down_sync(0xffffffffu, m2[i], off);
    }
    int wid = threadIdx.x>>5;
    if ((threadIdx.x&31)==0){
#pragma unroll
        for (int i=0;i<10;i++) red[wid][i]=m1[i];
#pragma unroll
        for (int i=0;i<55;i++) red[wid][10+i]=m2[i];
    }
    __syncthreads();
    if (threadIdx.x < 65){
        float a=0.f;
#pragma unroll
        for (int w=0;w<8;w++) a += red[w][threadIdx.x];
        if (threadIdx.x < 10) atomicAdd(&g_M1[threadIdx.x], a);
        else atomicAdd(&g_M2[threadIdx.x-10], a);
    }
}

__global__ void k_fold(const float* __restrict__ w1, const float* __restrict__ g1,
                       const float* __restrict__ be1){
    int d = threadIdx.x;
    const double invNK = 1.0/(double)NK;
    double wv[10];
#pragma unroll
    for (int c=0;c<10;c++) wv[c] = (double)w1[c*128+d];
    double m = 0.0;
#pragma unroll
    for (int c=0;c<10;c++) m += ((double)g_M1[c]*invNK)*wv[c];
    double q = 0.0; int t = 0;
#pragma unroll
    for (int a=0;a<10;a++)
#pragma unroll
        for (int b=a;b<10;b++){
            double s2 = (double)g_M2[t++]*invNK;
            double term = s2*wv[a]*wv[b];
            q += (a==b) ? term : 2.0*term;
        }
    double var = q - m*m;
    double a1 = (double)g1[d] / sqrt(var + 1e-5);
    g_c1[d] = (float)((double)be1[d] - m*a1);
#pragma unroll
    for (int c=0;c<10;c++) g_w1p[c*128+d] = (float)(wv[c]*a1);
}

__device__ __forceinline__ float w8row(int r, int c){
    switch(r){
        case 0: return g_w1p[384+c] - g_w1p[768+c];
        case 1: return g_w1p[512+c] - g_w1p[896+c];
        case 2: return g_w1p[640+c] - g_w1p[1024+c];
        case 3: return g_w1p[1152+c];
        case 4: return g_w1p[c]     + g_w1p[768+c];
        case 5: return g_w1p[128+c] + g_w1p[896+c];
        case 6: return g_w1p[256+c] + g_w1p[1024+c];
        default: return g_c1[c];
    }
}

__global__ void __launch_bounds__(NT,1) k_main(
    const float* __restrict__ p, const float* __restrict__ x,
    const float* __restrict__ w2, const float* __restrict__ b2,
    const float* __restrict__ ws)
{
    extern __shared__ float sm[];
    int tid = threadIdx.x, w = tid>>5, lid = tid&31;
    int g = lid>>2, tq = lid&3;
    int wl = w & 7;
    int rA = wl*16;
    bool lowhalf = (w < 8);
    int rg = w & 3, cg = w >> 2;
    int row0 = rg*32;

    // ---- stage weight fragments ----
    for (int i = tid; i < 2048; i += NT){
        int l2 = i&31, n2 = (i>>5)&3, K = i>>7;
        int g2 = l2>>2, t2 = l2&3;
        int r0 = K*8+t2, r1 = r0+4, c0 = n2*16+g2;
        float4 v;
        v.x = to_tf32(w2[r0*64+c0]);   v.y = to_tf32(w2[r1*64+c0]);
        v.z = to_tf32(w2[r0*64+c0+8]); v.w = to_tf32(w2[r1*64+c0+8]);
        *(float4*)&sm[F_W2F + i*4] = v;
    }
    for (int i = tid; i < 4096; i += NT){
        int l2 = i&31, n2 = (i>>5)&7, K = i>>8;
        int g2 = l2>>2, t2 = l2&3;
        int r0 = K*8+t2, r1 = r0+4, c0 = n2*16+g2;
        float4 v;
        v.x = to_tf32(ws[r0*128+c0]);   v.y = to_tf32(ws[r1*128+c0]);
        v.z = to_tf32(ws[r0*128+c0+8]); v.w = to_tf32(ws[r1*128+c0+8]);
        *(float4*)&sm[F_WSF + i*4] = v;
    }
    if (tid < 256){
        int i = tid, l2 = i&31, n2 = (i>>5)&7;
        int g2 = l2>>2, t2 = l2&3;
#pragma unroll
        for (int j=0;j<2;j++){
            int c = (2*n2+j)*8 + g2;
            float v0 = w8row(t2,   c);
            float v1 = w8row(t2+4, c);
            float h0 = to_tf32(v0), h1 = to_tf32(v1);
            sm[F_W1FH + (n2*32+l2)*4 + 2*j  ] = h0;
            sm[F_W1FH + (n2*32+l2)*4 + 2*j+1] = h1;
            sm[F_W1FL + (n2*32+l2)*4 + 2*j  ] = to_tf32(v0-h0);
            sm[F_W1FL + (n2*32+l2)*4 + 2*j+1] = to_tf32(v1-h1);
        }
    }
    if (tid < 64) sm[F_B2+tid]=b2[tid];
    __syncthreads();

    int xrow = wl*16 + (lid>>1);
    int xcol = (lowhalf?0:32) + (lid&1)*16;

    for (int t = blockIdx.x; t < NTILES; t += gridDim.x){
        const float4* xp = (const float4*)(x + ((size_t)t*128 + xrow)*64 + xcol);
        float4 xr[4];
#pragma unroll
        for (int i=0;i<4;i++) xr[i] = xp[i];

        if (tid < 96) *(float4*)&sm[F_PSM + tid*4] = *(const float4*)(p + (size_t)t*384 + tid*4);
        __syncthreads();

        if (tid < 128){
            int pt = tid>>4, k = tid&15;
            float cx=sm[F_PSM+pt*48],     cy=sm[F_PSM+pt*48+1],     cz=sm[F_PSM+pt*48+2];
            float qx=sm[F_PSM+pt*48+3*k], qy=sm[F_PSM+pt*48+3*k+1], qz=sm[F_PSM+pt*48+3*k+2];
            float dx=cx-qx, dy=cy-qy, dz=cz-qz;
            float ds = sqrtf(dx*dx+dy*dy+dz*dz);
            float vv[8] = {qx,qy,qz,ds,cx,cy,cz,1.f};
#pragma unroll
            for (int c=0;c<8;c++){
                float hi = to_tf32(vv[c]);
                sm[F_A1H + tid*12 + c] = hi;
                sm[F_A1L + tid*12 + c] = to_tf32(vv[c]-hi);
            }
        }
        __syncthreads();

        // ---- GEMM1 (K=8, split tf32): h = relu(A1 @ W8) ----
        {
            u32 ah0 = __float_as_uint(sm[F_A1H + (rA+g  )*12 + tq]);
            u32 ah1 = __float_as_uint(sm[F_A1H + (rA+g+8)*12 + tq]);
            u32 ah2 = __float_as_uint(sm[F_A1H + (rA+g  )*12 + tq+4]);
            u32 ah3 = __float_as_uint(sm[F_A1H + (rA+g+8)*12 + tq+4]);
            u32 al0 = __float_as_uint(sm[F_A1L + (rA+g  )*12 + tq]);
            u32 al1 = __float_as_uint(sm[F_A1L + (rA+g+8)*12 + tq]);
            u32 al2 = __float_as_uint(sm[F_A1L + (rA+g  )*12 + tq+4]);
            u32 al3 = __float_as_uint(sm[F_A1L + (rA+g+8)*12 + tq+4]);
            int n2b = lowhalf ? 0 : 4;
#pragma unroll
            for (int j=0;j<4;j++){
                int n2g = n2b + j;
                float4 bh = *(float4*)&sm[F_W1FH + (n2g*32+lid)*4];
                float4 bl = *(float4*)&sm[F_W1FL + (n2g*32+lid)*4];
#pragma unroll
                for (int par=0;par<2;par++){
                    float d[4] = {0.f,0.f,0.f,0.f};
                    u32 b0 = __float_as_uint(par? bh.z : bh.x);
                    u32 b1 = __float_as_uint(par? bh.w : bh.y);
                    u32 c0u= __float_as_uint(par? bl.z : bl.x);
                    u32 c1u= __float_as_uint(par? bl.w : bl.y);
                    mma4(d, ah0,ah1,ah2,ah3, b0,b1);
                    mma4(d, al0,al1,al2,al3, b0,b1);
                    mma4(d, ah0,ah1,ah2,ah3, c0u,c1u);
                    int c0 = (n2g*2+par)*8 + 2*tq;
                    float2 lo, hi;
                    lo.x = to_tf32(fmaxf(d[0],0.f)); lo.y = to_tf32(fmaxf(d[1],0.f));
                    hi.x = to_tf32(fmaxf(d[2],0.f)); hi.y = to_tf32(fmaxf(d[3],0.f));
                    *(float2*)&sm[F_ACT + (rA+g  )*132 + c0] = lo;
                    *(float2*)&sm[F_ACT + (rA+g+8)*132 + c0] = hi;
                }
            }
        }
        __syncthreads();

        // ---- GEMM2: p_c = h @ w2, register-double-buffered ----
        float d2[4][4];
#pragma unroll
        for (int n=0;n<4;n++){ d2[n][0]=0.f; d2[n][1]=0.f; d2[n][2]=0.f; d2[n][3]=0.f; }
        {
            int n2b = lowhalf ? 0 : 2;
            u32 aa[2][4]; float4 bb[2][2];
            {
                const float* ar = &sm[F_ACT + tq];
                aa[0][0]=__float_as_uint(ar[(rA+g  )*132]);
                aa[0][1]=__float_as_uint(ar[(rA+g+8)*132]);
                aa[0][2]=__float_as_uint(ar[(rA+g  )*132+4]);
                aa[0][3]=__float_as_uint(ar[(rA+g+8)*132+4]);
                bb[0][0]=*(float4*)&sm[F_W2F + ((n2b  )*32+lid)*4];
                bb[0][1]=*(float4*)&sm[F_W2F + ((n2b+1)*32+lid)*4];
            }
#pragma unroll
            for (int K=0;K<16;K++){
                int cur = K&1, nxt = cur^1;
                if (K < 15){
                    const float* ar = &sm[F_ACT + (K+1)*8 + tq];
                    aa[nxt][0]=__float_as_uint(ar[(rA+g  )*132]);
                    aa[nxt][1]=__float_as_uint(ar[(rA+g+8)*132]);
                    aa[nxt][2]=__float_as_uint(ar[(rA+g  )*132+4]);
                    aa[nxt][3]=__float_as_uint(ar[(rA+g+8)*132+4]);
                    bb[nxt][0]=*(float4*)&sm[F_W2F + (((K+1)*4+n2b  )*32+lid)*4];
                    bb[nxt][1]=*(float4*)&sm[F_W2F + (((K+1)*4+n2b+1)*32+lid)*4];
                }
                mma4(d2[0], aa[cur][0],aa[cur][1],aa[cur][2],aa[cur][3],
                     __float_as_uint(bb[cur][0].x), __float_as_uint(bb[cur][0].y));
                mma4(d2[1], aa[cur][0],aa[cur][1],aa[cur][2],aa[cur][3],
                     __float_as_uint(bb[cur][0].z), __float_as_uint(bb[cur][0].w));
                mma4(d2[2], aa[cur][0],aa[cur][1],aa[cur][2],aa[cur][3],
                     __float_as_uint(bb[cur][1].x), __float_as_uint(bb[cur][1].y));
                mma4(d2[3], aa[cur][0],aa[cur][1],aa[cur][2],aa[cur][3],
                     __float_as_uint(bb[cur][1].z), __float_as_uint(bb[cur][1].w));
            }
        }
        // write px = [p_c + b2 | x]
        {
            int nb = lowhalf ? 0 : 4;
#pragma unroll
            for (int n=0;n<4;n++){
                int c0 = (nb+n)*8 + 2*tq;
                float ba = sm[F_B2+c0], bb2 = sm[F_B2+c0+1];
                float2 lo, hi;
                lo.x = to_tf32(d2[n][0]+ba); lo.y = to_tf32(d2[n][1]+bb2);
                hi.x = to_tf32(d2[n][2]+ba); hi.y = to_tf32(d2[n][3]+bb2);
                *(float2*)&sm[F_ACT + (rA+g  )*132 + c0] = lo;
                *(float2*)&sm[F_ACT + (rA+g+8)*132 + c0] = hi;
            }
#pragma unroll
            for (int i=0;i<4;i++){
                float4 v = xr[i], wv;
                wv.x=to_tf32(v.x); wv.y=to_tf32(v.y); wv.z=to_tf32(v.z); wv.w=to_tf32(v.w);
                *(float4*)&sm[F_ACT + xrow*132 + 64 + xcol + i*4] = wv;
            }
        }
        __syncthreads();

        // ---- GEMM3: logits = px @ ws (mt=2, nt=4) ----
        float d3[2][4][4];
#pragma unroll
        for (int m=0;m<2;m++)
#pragma unroll
            for (int n=0;n<4;n++){ d3[m][n][0]=0.f; d3[m][n][1]=0.f; d3[m][n][2]=0.f; d3[m][n][3]=0.f; }
        {
#pragma unroll 4
            for (int K=0;K<16;K++){
                const float* ar = &sm[F_ACT + K*8 + tq];
                u32 a[2][4];
#pragma unroll
                for (int m=0;m<2;m++){
                    int rb = row0 + m*16;
                    a[m][0] = __float_as_uint(ar[(rb+g  )*132]);
                    a[m][1] = __float_as_uint(ar[(rb+g+8)*132]);
                    a[m][2] = __float_as_uint(ar[(rb+g  )*132+4]);
                    a[m][3] = __float_as_uint(ar[(rb+g+8)*132+4]);
                }
                float4 b0 = *(float4*)&sm[F_WSF + ((K*8 + 2*cg  )*32+lid)*4];
                float4 b1 = *(float4*)&sm[F_WSF + ((K*8 + 2*cg+1)*32+lid)*4];
#pragma unroll
                for (int m=0;m<2;m++){
                    mma4(d3[m][0], a[m][0],a[m][1],a[m][2],a[m][3], __float_as_uint(b0.x), __float_as_uint(b0.y));
                    mma4(d3[m][1], a[m][0],a[m][1],a[m][2],a[m][3], __float_as_uint(b0.z), __float_as_uint(b0.w));
                    mma4(d3[m][2], a[m][0],a[m][1],a[m][2],a[m][3], __float_as_uint(b1.x), __float_as_uint(b1.y));
                    mma4(d3[m][3], a[m][0],a[m][1],a[m][2],a[m][3], __float_as_uint(b1.z), __float_as_uint(b1.w));
                }
            }
        }

        // ---- softmax over k + pooled feat -> g_feat ----
#pragma unroll
        for (int m=0;m<2;m++){
            int pt = 2*rg + m;
            int rb = row0 + m*16;
#pragma unroll
            for (int nl=0; nl<4; nl++){
                int c0 = (4*cg+nl)*8 + 2*tq;
                float e0 = __expf(d3[m][nl][0]), e1 = __expf(d3[m][nl][1]);
                float e2 = __expf(d3[m][nl][2]), e3 = __expf(d3[m][nl][3]);
                float2 plo = *(float2*)&sm[F_ACT + (rb+g  )*132 + c0];
                float2 phi = *(float2*)&sm[F_ACT + (rb+g+8)*132 + c0];
                float se = e0+e2, so_ = e1+e3;
                float ve = fmaf(e0, plo.x, e2*phi.x);
                float vo = fmaf(e1, plo.y, e3*phi.y);
#pragma unroll
                for (int mm=4;mm<32;mm<<=1){
                    se += __shfl_xor_sync(0xffffffffu, se, mm);
                    so_ += __shfl_xor_sync(0xffffffffu, so_, mm);
                    ve += __shfl_xor_sync(0xffffffffu, ve, mm);
                    vo += __shfl_xor_sync(0xffffffffu, vo, mm);
                }
                if (lid < 4){
                    float2 f; f.x = ve/se; f.y = vo/so_;
                    *(float2*)&g_feat[((size_t)t*8 + pt)*128 + c0] = f;
                }
            }
        }
        __syncthreads();
    }
}

// ---- k_out: out = feat @ wo + bo, BN2 partials ----
__global__ void __launch_bounds__(ONT,1) k_out(const float* __restrict__ wo,
        const float* __restrict__ bo, float* __restrict__ out){
    extern __shared__ float so[];
    int tid = threadIdx.x, w = tid>>5, lid = tid&31;
    int g = lid>>2, tq = lid&3;
    for (int i = tid; i < 4096; i += ONT){      // FIXED: full 16 K-steps
        int l2 = i&31, n = (i>>5)&7, K = i>>8;
        int g2 = l2>>2, t2 = l2&3;
        float2 v;
        v.x = to_tf32(wo[(K*8+t2  )*64 + n*8+g2]);
        v.y = to_tf32(wo[(K*8+t2+4)*64 + n*8+g2]);
        *(float2*)&so[O_WOF + i*2] = v;
    }
    if (tid < 64){ so[O_BO+tid]=bo[tid]; so[O_BNS+tid]=0.f; so[O_BNQ+tid]=0.f; }
    {
        int row = tid>>1, ch = (tid&1)*64;
        const float4* fp = (const float4*)(g_feat + ((size_t)blockIdx.x*128 + row)*128 + ch);
#pragma unroll
        for (int i=0;i<16;i++)
            *(float4*)&so[O_FT + row*132 + ch + i*4] = fp[i];
    }
    __syncthreads();
    float d[8][4];
#pragma unroll
    for (int n=0;n<8;n++){ d[n][0]=0.f; d[n][1]=0.f; d[n][2]=0.f; d[n][3]=0.f; }
#pragma unroll 4
    for (int K=0;K<16;K++){
        const float* ar = &so[O_FT + (w*16)*132 + K*8 + tq];
        u32 a0 = __float_as_uint(ar[g*132]);
        u32 a1 = __float_as_uint(ar[(g+8)*132]);
        u32 a2 = __float_as_uint(ar[g*132+4]);
        u32 a3 = __float_as_uint(ar[(g+8)*132+4]);
#pragma unroll
        for (int n=0;n<8;n++){
            float2 bv = *(float2*)&so[O_WOF + ((K*8+n)*32+lid)*2];
            mma4(d[n], a0,a1,a2,a3, __float_as_uint(bv.x), __float_as_uint(bv.y));
        }
    }
    size_t rbase = (size_t)blockIdx.x*128 + w*16;
#pragma unroll
    for (int n=0;n<8;n++){
        int c0 = n*8 + 2*tq;
        float ba = so[O_BO+c0], bb = so[O_BO+c0+1];
        float v0 = d[n][0]+ba, v1 = d[n][1]+bb;
        float v2 = d[n][2]+ba, v3 = d[n][3]+bb;
        float2 lo, hi;
        lo.x=v0; lo.y=v1; hi.x=v2; hi.y=v3;
        *(float2*)&out[(rbase+g  )*64 + c0] = lo;
        *(float2*)&out[(rbase+g+8)*64 + c0] = hi;
        atomicAdd(&so[O_BNS+c0],   v0+v2);
        atomicAdd(&so[O_BNS+c0+1], v1+v3);
        atomicAdd(&so[O_BNQ+c0],   fmaf(v0,v0,v2*v2));
        atomicAdd(&so[O_BNQ+c0+1], fmaf(v1,v1,v3*v3));
    }
    __syncthreads();
    if (tid < 64){
        atomicAdd(&g_sum2[tid],   so[O_BNS+tid]);
        atomicAdd(&g_sumsq2[tid], so[O_BNQ+tid]);
    }
}

__global__ void k_fin(const float* __restrict__ g2, const float* __restrict__ be2){
    int j = threadIdx.x;
    double inv = 1.0/(double)Nn;
    double mu  = (double)g_sum2[j]*inv;
    double var = (double)g_sumsq2[j]*inv - mu*mu;
    double a2  = (double)g2[j] / sqrt(var + 1e-5);
    g_a2[j] = (float)a2;
    g_c2[j] = (float)((double)be2[j] - mu*a2);
}

__global__ void k_norm(float* __restrict__ out){
    __shared__ float a2s[64], c2s[64];
    if (threadIdx.x < 64){ a2s[threadIdx.x]=g_a2[threadIdx.x]; c2s[threadIdx.x]=g_c2[threadIdx.x]; }
    __syncthreads();
    const int nq = Nn*64/4;
    float4* o4 = (float4*)out;
    for (int f = blockIdx.x*blockDim.x + threadIdx.x; f < nq; f += gridDim.x*blockDim.x){
        float4 v = o4[f];
        int j = (f*4) & 63;
        v.x = fmaxf(fmaf(v.x, a2s[j],   c2s[j]),   0.f);
        v.y = fmaxf(fmaf(v.y, a2s[j+1], c2s[j+1]), 0.f);
        v.z = fmaxf(fmaf(v.z, a2s[j+2], c2s[j+2]), 0.f);
        v.w = fmaxf(fmaf(v.w, a2s[j+3], c2s[j+3]), 0.f);
        o4[f] = v;
    }
}

extern "C" void kernel_launch(void* const* d_in, const int* in_sizes, int n_in,
                              void* d_out, int out_size){
    const float* p   = (const float*)d_in[0];
    const float* x   = (const float*)d_in[1];
    const float* w1  = (const float*)d_in[2];
    const float* g1  = (const float*)d_in[4];
    const float* be1 = (const float*)d_in[5];
    const float* w2  = (const float*)d_in[6];
    const float* b2  = (const float*)d_in[7];
    const float* ws  = (const float*)d_in[8];
    const float* wo  = (const float*)d_in[9];
    const float* bo  = (const float*)d_in[10];
    const float* g2  = (const float*)d_in[11];
    const float* be2 = (const float*)d_in[12];
    float* out = (float*)d_out;
    (void)in_sizes; (void)n_in; (void)out_size;

    cudaFuncSetAttribute(k_main, cudaFuncAttributeMaxDynamicSharedMemorySize, SMEM_BYTES);
    cudaFuncSetAttribute(k_out,  cudaFuncAttributeMaxDynamicSharedMemorySize, OSMEM_BYTES);

    k_zero<<<1,64>>>();
    k_stats<<<256,256>>>(p);
    k_fold<<<1,128>>>(w1,g1,be1);
    k_main<<<GRID_MAIN,NT,SMEM_BYTES>>>(p,x,w2,b2,ws);
    k_out<<<Nn/128,ONT,OSMEM_BYTES>>>(wo,bo,out);
    k_fin<<<1,64>>>(g2,be2);
    k_norm<<<2048,256>>>(out);
}

// round 12
// speedup vs baseline: 1.6020x; 1.6020x over previous
#include <cuda_runtime.h>
typedef unsigned int u32;

#define Nn 65536
#define NK (Nn*16)
#define NTILES (Nn/8)
#define NT 512
#define GRID_MAIN 148

// ---- k_main float offsets in dynamic smem ----
#define F_ACT   0          // 128 x 132 A-tile (h, then px)
#define F_A1H   16896
#define F_A1L   18432
#define F_W1FH  19968
#define F_W1FL  20992
#define F_W2F   22016      // w2 frags (8192 floats)
#define F_WSF   30208      // ws frags (16384 floats)
#define F_WOF   46592      // wo frags (8192 floats)
#define F_FEAT  54784      // 16 x 132 (two tiles)
#define F_B2    56896
#define F_BO    56960
#define F_BNS   57024
#define F_BNQ   57088
#define F_TOTAL 57152
#define SMEM_BYTES (F_TOTAL*4)

__device__ __forceinline__ float to_tf32(float x){
    float r; asm("cvt.rna.tf32.f32 %0, %1;":"=f"(r):"f"(x)); return r;
}
__device__ __forceinline__ void mma4(float* d, u32 a0, u32 a1, u32 a2, u32 a3,
                                     u32 b0, u32 b1){
    asm volatile("mma.sync.aligned.m16n8k8.row.col.f32.tf32.tf32.f32 "
        "{%0,%1,%2,%3}, {%4,%5,%6,%7}, {%8,%9}, {%0,%1,%2,%3};"
        : "+f"(d[0]),"+f"(d[1]),"+f"(d[2]),"+f"(d[3])
        : "r"(a0),"r"(a1),"r"(a2),"r"(a3),"r"(b0),"r"(b1));
}

// ---- scratch globals ----
__device__ float g_M1[10], g_M2[55], g_w1p[1280], g_c1[128];
__device__ float g_sum2[64], g_sumsq2[64], g_a2[64], g_c2[64];

__global__ void k_zero(){
    int t = threadIdx.x;
    if (t < 10) g_M1[t]=0.f;
    if (t < 55) g_M2[t]=0.f;
    if (t < 64){ g_sum2[t]=0.f; g_sumsq2[t]=0.f; }
}

// ---- K1: concat moments, center-factored ----
__global__ void k_stats(const float* __restrict__ p){
    __shared__ float red[8][65];
    float m1[10], m2[55];
#pragma unroll
    for (int i=0;i<10;i++) m1[i]=0.f;
#pragma unroll
    for (int i=0;i<55;i++) m2[i]=0.f;

    int n = blockIdx.x*blockDim.x + threadIdx.x;
    {
        float4 pr[12];
        const float4* pp = (const float4*)(p + (size_t)n*48);
#pragma unroll
        for (int i=0;i<12;i++) pr[i] = pp[i];
        const float* pc = (const float*)pr;
        float C0=pc[0], C1=pc[1], C2=pc[2];
        float Sq0=0.f,Sq1=0.f,Sq2=0.f;
        float Q00=0.f,Q01=0.f,Q02=0.f,Q11=0.f,Q12=0.f,Q22=0.f;
        float Sd=0.f, Sdq0=0.f,Sdq1=0.f,Sdq2=0.f, Sdd=0.f;
#pragma unroll
        for (int k=0;k<16;k++){
            float qx=pc[3*k], qy=pc[3*k+1], qz=pc[3*k+2];
            float dx=C0-qx, dy=C1-qy, dz=C2-qz;
            float d2 = dx*dx + dy*dy + dz*dz;
            float ds = sqrtf(d2);
            Sq0+=qx; Sq1+=qy; Sq2+=qz;
            Q00=fmaf(qx,qx,Q00); Q01=fmaf(qx,qy,Q01); Q02=fmaf(qx,qz,Q02);
            Q11=fmaf(qy,qy,Q11); Q12=fmaf(qy,qz,Q12); Q22=fmaf(qz,qz,Q22);
            Sd+=ds; Sdq0=fmaf(ds,qx,Sdq0); Sdq1=fmaf(ds,qy,Sdq1); Sdq2=fmaf(ds,qz,Sdq2);
            Sdd+=d2;
        }
        float C[3]={C0,C1,C2};
        float Sq[3]={Sq0,Sq1,Sq2};
        float QQ[3][3]={{Q00,Q01,Q02},{Q01,Q11,Q12},{Q02,Q12,Q22}};
        float SDQ[3]={Sdq0,Sdq1,Sdq2};
#pragma unroll
        for (int i=0;i<3;i++){
            m1[i]   += 16.f*C[i];
            m1[3+i] += Sq[i];
            m1[6+i] += 16.f*C[i]-Sq[i];
        }
        m1[9] += Sd;
        int t = 0;
#pragma unroll
        for (int a=0;a<3;a++){
#pragma unroll
            for (int b=a;b<3;b++) m2[t++] += 16.f*C[a]*C[b];
#pragma unroll
            for (int b=0;b<3;b++) m2[t++] += C[a]*Sq[b];
#pragma unroll
            for (int b=0;b<3;b++) m2[t++] += C[a]*(16.f*C[b]-Sq[b]);
            m2[t++] += C[a]*Sd;
        }
#pragma unroll
        for (int a=0;a<3;a++){
#pragma unroll
            for (int b=a;b<3;b++) m2[t++] += QQ[a][b];
#pragma unroll
            for (int b=0;b<3;b++) m2[t++] += C[b]*Sq[a]-QQ[a][b];
            m2[t++] += SDQ[a];
        }
#pragma unroll
        for (int a=0;a<3;a++){
#pragma unroll
            for (int b=a;b<3;b++)
                m2[t++] += 16.f*C[a]*C[b]-C[a]*Sq[b]-C[b]*Sq[a]+QQ[a][b];
            m2[t++] += C[a]*Sd - SDQ[a];
        }
        m2[t++] += Sdd;
    }
#pragma unroll
    for (int off=16; off>0; off>>=1){
#pragma unroll
        for (int i=0;i<10;i++) m1[i] += __shfl_down_sync(0xffffffffu, m1[i], off);
#pragma unroll
        for (int i=0;i<55;i++) m2[i] += __shfl_down_sync(0xffffffffu, m2[i], off);
    }
    int wid = threadIdx.x>>5;
    if ((threadIdx.x&31)==0){
#pragma unroll
        for (int i=0;i<10;i++) red[wid][i]=m1[i];
#pragma unroll
        for (int i=0;i<55;i++) red[wid][10+i]=m2[i];
    }
    __syncthreads();
    if (threadIdx.x < 65){
        float a=0.f;
#pragma unroll
        for (int w=0;w<8;w++) a += red[w][threadIdx.x];
        if (threadIdx.x < 10) atomicAdd(&g_M1[threadIdx.x], a);
        else atomicAdd(&g_M2[threadIdx.x-10], a);
    }
}

__global__ void k_fold(const float* __restrict__ w1, const float* __restrict__ g1,
                       const float* __restrict__ be1){
    int d = threadIdx.x;
    const double invNK = 1.0/(double)NK;
    double wv[10];
#pragma unroll
    for (int c=0;c<10;c++) wv[c] = (double)w1[c*128+d];
    double m = 0.0;
#pragma unroll
    for (int c=0;c<10;c++) m += ((double)g_M1[c]*invNK)*wv[c];
    double q = 0.0; int t = 0;
#pragma unroll
    for (int a=0;a<10;a++)
#pragma unroll
        for (int b=a;b<10;b++){
            double s2 = (double)g_M2[t++]*invNK;
            double term = s2*wv[a]*wv[b];
            q += (a==b) ? term : 2.0*term;
        }
    double var = q - m*m;
    double a1 = (double)g1[d] / sqrt(var + 1e-5);
    g_c1[d] = (float)((double)be1[d] - m*a1);
#pragma unroll
    for (int c=0;c<10;c++) g_w1p[c*128+d] = (float)(wv[c]*a1);
}

__device__ __forceinline__ float w8row(int r, int c){
    switch(r){
        case 0: return g_w1p[384+c] - g_w1p[768+c];
        case 1: return g_w1p[512+c] - g_w1p[896+c];
        case 2: return g_w1p[640+c] - g_w1p[1024+c];
        case 3: return g_w1p[1152+c];
        case 4: return g_w1p[c]     + g_w1p[768+c];
        case 5: return g_w1p[128+c] + g_w1p[896+c];
        case 6: return g_w1p[256+c] + g_w1p[1024+c];
        default: return g_c1[c];
    }
}

__global__ void __launch_bounds__(NT,1) k_main(
    const float* __restrict__ p, const float* __restrict__ x,
    const float* __restrict__ w2, const float* __restrict__ b2,
    const float* __restrict__ ws, const float* __restrict__ wo,
    const float* __restrict__ bo, float* __restrict__ out)
{
    extern __shared__ float sm[];
    int tid = threadIdx.x, w = tid>>5, lid = tid&31;
    int g = lid>>2, tq = lid&3;
    int wl = w & 7;
    int rA = wl*16;
    bool lowhalf = (w < 8);
    int rg = w & 3, cg = w >> 2;
    int row0 = rg*32;

    // ---- stage weight fragments ----
    for (int i = tid; i < 2048; i += NT){
        int l2 = i&31, n2 = (i>>5)&3, K = i>>7;
        int g2 = l2>>2, t2 = l2&3;
        int r0 = K*8+t2, r1 = r0+4, c0 = n2*16+g2;
        float4 v;
        v.x = to_tf32(w2[r0*64+c0]);   v.y = to_tf32(w2[r1*64+c0]);
        v.z = to_tf32(w2[r0*64+c0+8]); v.w = to_tf32(w2[r1*64+c0+8]);
        *(float4*)&sm[F_W2F + i*4] = v;
    }
    for (int i = tid; i < 4096; i += NT){
        int l2 = i&31, n2 = (i>>5)&7, K = i>>8;
        int g2 = l2>>2, t2 = l2&3;
        int r0 = K*8+t2, r1 = r0+4, c0 = n2*16+g2;
        float4 v;
        v.x = to_tf32(ws[r0*128+c0]);   v.y = to_tf32(ws[r1*128+c0]);
        v.z = to_tf32(ws[r0*128+c0+8]); v.w = to_tf32(ws[r1*128+c0+8]);
        *(float4*)&sm[F_WSF + i*4] = v;
    }
    for (int i = tid; i < 4096; i += NT){        // wo: [K(16)][n(8)][lid] float2
        int l2 = i&31, n = (i>>5)&7, K = i>>8;
        int g2 = l2>>2, t2 = l2&3;
        float2 v;
        v.x = to_tf32(wo[(K*8+t2  )*64 + n*8+g2]);
        v.y = to_tf32(wo[(K*8+t2+4)*64 + n*8+g2]);
        *(float2*)&sm[F_WOF + i*2] = v;
    }
    if (tid < 256){
        int i = tid, l2 = i&31, n2 = (i>>5)&7;
        int g2 = l2>>2, t2 = l2&3;
#pragma unroll
        for (int j=0;j<2;j++){
            int c = (2*n2+j)*8 + g2;
            float v0 = w8row(t2,   c);
            float v1 = w8row(t2+4, c);
            float h0 = to_tf32(v0), h1 = to_tf32(v1);
            sm[F_W1FH + (n2*32+l2)*4 + 2*j  ] = h0;
            sm[F_W1FH + (n2*32+l2)*4 + 2*j+1] = h1;
            sm[F_W1FL + (n2*32+l2)*4 + 2*j  ] = to_tf32(v0-h0);
            sm[F_W1FL + (n2*32+l2)*4 + 2*j+1] = to_tf32(v1-h1);
        }
    }
    if (tid < 64){ sm[F_B2+tid]=b2[tid]; sm[F_BO+tid]=bo[tid]; sm[F_BNS+tid]=0.f; sm[F_BNQ+tid]=0.f; }
    __syncthreads();

    float bs0=0.f, bs1=0.f, bq0=0.f, bq1=0.f;
    int xrow = wl*16 + (lid>>1);
    int xcol = (lowhalf?0:32) + (lid&1)*16;
    int half = 0, tprev = 0;

    for (int t = blockIdx.x; t < NTILES; t += gridDim.x){
        const float4* xp = (const float4*)(x + ((size_t)t*128 + xrow)*64 + xcol);
        float4 xr[4];
#pragma unroll
        for (int i=0;i<4;i++) xr[i] = xp[i];

        // build layer1 A (hi/lo) straight from global p
        if (tid < 128){
            int pt = tid>>4, k = tid&15;
            const float* pb = p + (size_t)t*384 + pt*48;
            float cx=pb[0], cy=pb[1], cz=pb[2];
            float qx=pb[3*k], qy=pb[3*k+1], qz=pb[3*k+2];
            float dx=cx-qx, dy=cy-qy, dz=cz-qz;
            float ds = sqrtf(dx*dx+dy*dy+dz*dz);
            float vv[8] = {qx,qy,qz,ds,cx,cy,cz,1.f};
#pragma unroll
            for (int c=0;c<8;c++){
                float hi = to_tf32(vv[c]);
                sm[F_A1H + tid*12 + c] = hi;
                sm[F_A1L + tid*12 + c] = to_tf32(vv[c]-hi);
            }
        }
        __syncthreads();

        // ---- GEMM1 (K=8, split tf32): h = relu(A1 @ W8) ----
        {
            u32 ah0 = __float_as_uint(sm[F_A1H + (rA+g  )*12 + tq]);
            u32 ah1 = __float_as_uint(sm[F_A1H + (rA+g+8)*12 + tq]);
            u32 ah2 = __float_as_uint(sm[F_A1H + (rA+g  )*12 + tq+4]);
            u32 ah3 = __float_as_uint(sm[F_A1H + (rA+g+8)*12 + tq+4]);
            u32 al0 = __float_as_uint(sm[F_A1L + (rA+g  )*12 + tq]);
            u32 al1 = __float_as_uint(sm[F_A1L + (rA+g+8)*12 + tq]);
            u32 al2 = __float_as_uint(sm[F_A1L + (rA+g  )*12 + tq+4]);
            u32 al3 = __float_as_uint(sm[F_A1L + (rA+g+8)*12 + tq+4]);
            int n2b = lowhalf ? 0 : 4;
#pragma unroll
            for (int j=0;j<4;j++){
                int n2g = n2b + j;
                float4 bh = *(float4*)&sm[F_W1FH + (n2g*32+lid)*4];
                float4 bl = *(float4*)&sm[F_W1FL + (n2g*32+lid)*4];
#pragma unroll
                for (int par=0;par<2;par++){
                    float d[4] = {0.f,0.f,0.f,0.f};
                    u32 b0 = __float_as_uint(par? bh.z : bh.x);
                    u32 b1 = __float_as_uint(par? bh.w : bh.y);
                    u32 c0u= __float_as_uint(par? bl.z : bl.x);
                    u32 c1u= __float_as_uint(par? bl.w : bl.y);
                    mma4(d, ah0,ah1,ah2,ah3, b0,b1);
                    mma4(d, al0,al1,al2,al3, b0,b1);
                    mma4(d, ah0,ah1,ah2,ah3, c0u,c1u);
                    int c0 = (n2g*2+par)*8 + 2*tq;
                    float2 lo, hi;
                    lo.x = to_tf32(fmaxf(d[0],0.f)); lo.y = to_tf32(fmaxf(d[1],0.f));
                    hi.x = to_tf32(fmaxf(d[2],0.f)); hi.y = to_tf32(fmaxf(d[3],0.f));
                    *(float2*)&sm[F_ACT + (rA+g  )*132 + c0] = lo;
                    *(float2*)&sm[F_ACT + (rA+g+8)*132 + c0] = hi;
                }
            }
        }
        __syncthreads();

        // ---- GEMM2: p_c = h @ w2 (simple R7 loop) ----
        float d2[4][4];
#pragma unroll
        for (int n=0;n<4;n++){ d2[n][0]=0.f; d2[n][1]=0.f; d2[n][2]=0.f; d2[n][3]=0.f; }
        {
            int n2b = lowhalf ? 0 : 2;
#pragma unroll 4
            for (int K=0;K<16;K++){
                const float* ar = &sm[F_ACT + K*8 + tq];
                u32 a0 = __float_as_uint(ar[(rA+g  )*132]);
                u32 a1 = __float_as_uint(ar[(rA+g+8)*132]);
                u32 a2 = __float_as_uint(ar[(rA+g  )*132+4]);
                u32 a3 = __float_as_uint(ar[(rA+g+8)*132+4]);
                float4 b0 = *(float4*)&sm[F_W2F + ((K*4+n2b  )*32+lid)*4];
                float4 b1 = *(float4*)&sm[F_W2F + ((K*4+n2b+1)*32+lid)*4];
                mma4(d2[0], a0,a1,a2,a3, __float_as_uint(b0.x), __float_as_uint(b0.y));
                mma4(d2[1], a0,a1,a2,a3, __float_as_uint(b0.z), __float_as_uint(b0.w));
                mma4(d2[2], a0,a1,a2,a3, __float_as_uint(b1.x), __float_as_uint(b1.y));
                mma4(d2[3], a0,a1,a2,a3, __float_as_uint(b1.z), __float_as_uint(b1.w));
            }
        }
        // write px = [p_c + b2 | x]
        {
            int nb = lowhalf ? 0 : 4;
#pragma unroll
            for (int n=0;n<4;n++){
                int c0 = (nb+n)*8 + 2*tq;
                float ba = sm[F_B2+c0], bb2 = sm[F_B2+c0+1];
                float2 lo, hi;
                lo.x = to_tf32(d2[n][0]+ba); lo.y = to_tf32(d2[n][1]+bb2);
                hi.x = to_tf32(d2[n][2]+ba); hi.y = to_tf32(d2[n][3]+bb2);
                *(float2*)&sm[F_ACT + (rA+g  )*132 + c0] = lo;
                *(float2*)&sm[F_ACT + (rA+g+8)*132 + c0] = hi;
            }
#pragma unroll
            for (int i=0;i<4;i++){
                float4 v = xr[i], wv;
                wv.x=to_tf32(v.x); wv.y=to_tf32(v.y); wv.z=to_tf32(v.z); wv.w=to_tf32(v.w);
                *(float4*)&sm[F_ACT + xrow*132 + 64 + xcol + i*4] = wv;
            }
        }
        __syncthreads();

        // ---- GEMM3: logits = px @ ws (mt=2, nt=4) ----
        float d3[2][4][4];
#pragma unroll
        for (int m=0;m<2;m++)
#pragma unroll
            for (int n=0;n<4;n++){ d3[m][n][0]=0.f; d3[m][n][1]=0.f; d3[m][n][2]=0.f; d3[m][n][3]=0.f; }
        {
#pragma unroll 4
            for (int K=0;K<16;K++){
                const float* ar = &sm[F_ACT + K*8 + tq];
                u32 a[2][4];
#pragma unroll
                for (int m=0;m<2;m++){
                    int rb = row0 + m*16;
                    a[m][0] = __float_as_uint(ar[(rb+g  )*132]);
                    a[m][1] = __float_as_uint(ar[(rb+g+8)*132]);
                    a[m][2] = __float_as_uint(ar[(rb+g  )*132+4]);
                    a[m][3] = __float_as_uint(ar[(rb+g+8)*132+4]);
                }
                float4 b0 = *(float4*)&sm[F_WSF + ((K*8 + 2*cg  )*32+lid)*4];
                float4 b1 = *(float4*)&sm[F_WSF + ((K*8 + 2*cg+1)*32+lid)*4];
#pragma unroll
                for (int m=0;m<2;m++){
                    mma4(d3[m][0], a[m][0],a[m][1],a[m][2],a[m][3], __float_as_uint(b0.x), __float_as_uint(b0.y));
                    mma4(d3[m][1], a[m][0],a[m][1],a[m][2],a[m][3], __float_as_uint(b0.z), __float_as_uint(b0.w));
                    mma4(d3[m][2], a[m][0],a[m][1],a[m][2],a[m][3], __float_as_uint(b1.x), __float_as_uint(b1.y));
                    mma4(d3[m][3], a[m][0],a[m][1],a[m][2],a[m][3], __float_as_uint(b1.z), __float_as_uint(b1.w));
                }
            }
        }

        // ---- softmax over k + pooled feat -> FEAT rows [half*8 .. half*8+7] ----
        {
            int fbase = half*8;
#pragma unroll
            for (int m=0;m<2;m++){
                int pt = 2*rg + m;
                int rb = row0 + m*16;
#pragma unroll
                for (int nl=0; nl<4; nl++){
                    int c0 = (4*cg+nl)*8 + 2*tq;
                    float e0 = __expf(d3[m][nl][0]), e1 = __expf(d3[m][nl][1]);
                    float e2 = __expf(d3[m][nl][2]), e3 = __expf(d3[m][nl][3]);
                    float2 plo = *(float2*)&sm[F_ACT + (rb+g  )*132 + c0];
                    float2 phi = *(float2*)&sm[F_ACT + (rb+g+8)*132 + c0];
                    float se = e0+e2, so_ = e1+e3;
                    float ve = fmaf(e0, plo.x, e2*phi.x);
                    float vo = fmaf(e1, plo.y, e3*phi.y);
#pragma unroll
                    for (int mm=4;mm<32;mm<<=1){
                        se += __shfl_xor_sync(0xffffffffu, se, mm);
                        so_ += __shfl_xor_sync(0xffffffffu, so_, mm);
                        ve += __shfl_xor_sync(0xffffffffu, ve, mm);
                        vo += __shfl_xor_sync(0xffffffffu, vo, mm);
                    }
                    if (lid < 4){
                        float2 f; f.x = ve/se; f.y = vo/so_;
                        *(float2*)&sm[F_FEAT + (fbase+pt)*132 + c0] = f;
                    }
                }
            }
        }

        if (half == 0){
            tprev = t; half = 1;
            __syncthreads();
        } else {
            __syncthreads();
            // ---- paired epilogue: out[tprev points | t points] = FEAT(16x128) @ wo ----
            if (lowhalf){
                float d[4] = {0.f,0.f,0.f,0.f};
#pragma unroll 4
                for (int K=0;K<16;K++){
                    const float* ar = &sm[F_FEAT + K*8 + tq];
                    u32 a0 = __float_as_uint(ar[g*132]);
                    u32 a1 = __float_as_uint(ar[(g+8)*132]);
                    u32 a2 = __float_as_uint(ar[g*132+4]);
                    u32 a3 = __float_as_uint(ar[(g+8)*132+4]);
                    float2 bv = *(float2*)&sm[F_WOF + ((K*8+w)*32+lid)*2];
                    mma4(d, a0,a1,a2,a3, __float_as_uint(bv.x), __float_as_uint(bv.y));
                }
                int c0 = w*8 + 2*tq;
                float ba = sm[F_BO+c0], bb = sm[F_BO+c0+1];
                float v0 = d[0]+ba, v1 = d[1]+bb;   // row g   -> tprev point g
                float v2 = d[2]+ba, v3 = d[3]+bb;   // row g+8 -> t     point g
                float2 va; va.x=v0; va.y=v1;
                float2 vb; vb.x=v2; vb.y=v3;
                *(float2*)&out[((size_t)tprev*8 + g)*64 + c0] = va;
                *(float2*)&out[((size_t)t*8     + g)*64 + c0] = vb;
                bs0 += v0+v2; bq0 += fmaf(v0,v0,v2*v2);
                bs1 += v1+v3; bq1 += fmaf(v1,v1,v3*v3);
            }
            half = 0;
        }
    }

    // ---- tail: one unpaired tile left in FEAT rows 0-7 ----
    if (half && lowhalf){
        float d[4] = {0.f,0.f,0.f,0.f};
#pragma unroll 4
        for (int K=0;K<16;K++){
            const float* ar = &sm[F_FEAT + K*8 + tq];
            u32 a0 = __float_as_uint(ar[g*132]);
            u32 a1 = __float_as_uint(ar[(g+8)*132]);   // stale, unused rows
            u32 a2 = __float_as_uint(ar[g*132+4]);
            u32 a3 = __float_as_uint(ar[(g+8)*132+4]);
            float2 bv = *(float2*)&sm[F_WOF + ((K*8+w)*32+lid)*2];
            mma4(d, a0,a1,a2,a3, __float_as_uint(bv.x), __float_as_uint(bv.y));
        }
        int c0 = w*8 + 2*tq;
        float ba = sm[F_BO+c0], bb = sm[F_BO+c0+1];
        float v0 = d[0]+ba, v1 = d[1]+bb;
        float2 va; va.x=v0; va.y=v1;
        *(float2*)&out[((size_t)tprev*8 + g)*64 + c0] = va;
        bs0 += v0; bq0 += v0*v0;
        bs1 += v1; bq1 += v1*v1;
    }

    if (lowhalf){
        int c0 = w*8 + 2*tq;
        atomicAdd(&sm[F_BNS+c0  ], bs0);
        atomicAdd(&sm[F_BNS+c0+1], bs1);
        atomicAdd(&sm[F_BNQ+c0  ], bq0);
        atomicAdd(&sm[F_BNQ+c0+1], bq1);
    }
    __syncthreads();
    if (tid < 64){
        atomicAdd(&g_sum2[tid],   sm[F_BNS+tid]);
        atomicAdd(&g_sumsq2[tid], sm[F_BNQ+tid]);
    }
}

__global__ void k_fin(const float* __restrict__ g2, const float* __restrict__ be2){
    int j = threadIdx.x;
    double inv = 1.0/(double)Nn;
    double mu  = (double)g_sum2[j]*inv;
    double var = (double)g_sumsq2[j]*inv - mu*mu;
    double a2  = (double)g2[j] / sqrt(var + 1e-5);
    g_a2[j] = (float)a2;
    g_c2[j] = (float)((double)be2[j] - mu*a2);
}

__global__ void k_norm(float* __restrict__ out){
    __shared__ float a2s[64], c2s[64];
    if (threadIdx.x < 64){ a2s[threadIdx.x]=g_a2[threadIdx.x]; c2s[threadIdx.x]=g_c2[threadIdx.x]; }
    __syncthreads();
    const int nq = Nn*64/4;
    float4* o4 = (float4*)out;
    for (int f = blockIdx.x*blockDim.x + threadIdx.x; f < nq; f += gridDim.x*blockDim.x){
        float4 v = o4[f];
        int j = (f*4) & 63;
        v.x = fmaxf(fmaf(v.x, a2s[j],   c2s[j]),   0.f);
        v.y = fmaxf(fmaf(v.y, a2s[j+1], c2s[j+1]), 0.f);
        v.z = fmaxf(fmaf(v.z, a2s[j+2], c2s[j+2]), 0.f);
        v.w = fmaxf(fmaf(v.w, a2s[j+3], c2s[j+3]), 0.f);
        o4[f] = v;
    }
}

extern "C" void kernel_launch(void* const* d_in, const int* in_sizes, int n_in,
                              void* d_out, int out_size){
    const float* p   = (const float*)d_in[0];
    const float* x   = (const float*)d_in[1];
    const float* w1  = (const float*)d_in[2];
    const float* g1  = (const float*)d_in[4];
    const float* be1 = (const float*)d_in[5];
    const float* w2  = (const float*)d_in[6];
    const float* b2  = (const float*)d_in[7];
    const float* ws  = (const float*)d_in[8];
    const float* wo  = (const float*)d_in[9];
    const float* bo  = (const float*)d_in[10];
    const float* g2  = (const float*)d_in[11];
    const float* be2 = (const float*)d_in[12];
    float* out = (float*)d_out;
    (void)in_sizes; (void)n_in; (void)out_size;

    cudaFuncSetAttribute(k_main, cudaFuncAttributeMaxDynamicSharedMemorySize, SMEM_BYTES);

    k_zero<<<1,64>>>();
    k_stats<<<256,256>>>(p);
    k_fold<<<1,128>>>(w1,g1,be1);
    k_main<<<GRID_MAIN,NT,SMEM_BYTES>>>(p,x,w2,b2,ws,wo,bo,out);
    k_fin<<<1,64>>>(g2,be2);
    k_norm<<<2048,256>>>(out);
}

// round 13
// speedup vs baseline: 2.1843x; 1.3635x over previous
#include <cuda_runtime.h>
#include <cuda_fp16.h>
typedef unsigned int u32;

#define Nn 65536
#define NK (Nn*16)
#define NTILES (Nn/8)
#define NT 512
#define GRID_MAIN 148

// ---- k_main float offsets in dynamic smem ----
#define F_ACT   0          // halves: 128 x 136 (h, then px)  = 8704 floats
#define F_A1H   8704       // 128 x 12 fp32
#define F_A1L   10240
#define F_W1FH  11776      // 1024
#define F_W1FL  12800      // 1024
#define F_W2F   13824      // fp16 frags [K8][np4][lane] float4 = 4096
#define F_WSF   17920      // fp16 frags [K8][np8][lane] float4 = 8192
#define F_WOF   26112      // fp16 frags [K8][n8][lane] float2  = 4096
#define F_FEAT  30208      // halves: 16 x 136 = 1088 floats
#define F_B2    31296
#define F_BO    31360
#define F_BNS   31424
#define F_BNQ   31488
#define F_TOTAL 31552
#define SMEM_BYTES (F_TOTAL*4)

__device__ __forceinline__ float to_tf32(float x){
    float r; asm("cvt.rna.tf32.f32 %0, %1;":"=f"(r):"f"(x)); return r;
}
__device__ __forceinline__ void mma4(float* d, u32 a0, u32 a1, u32 a2, u32 a3,
                                     u32 b0, u32 b1){
    asm volatile("mma.sync.aligned.m16n8k8.row.col.f32.tf32.tf32.f32 "
        "{%0,%1,%2,%3}, {%4,%5,%6,%7}, {%8,%9}, {%0,%1,%2,%3};"
        : "+f"(d[0]),"+f"(d[1]),"+f"(d[2]),"+f"(d[3])
        : "r"(a0),"r"(a1),"r"(a2),"r"(a3),"r"(b0),"r"(b1));
}
__device__ __forceinline__ void mma16(float* d, u32 a0, u32 a1, u32 a2, u32 a3,
                                      u32 b0, u32 b1){
    asm volatile("mma.sync.aligned.m16n8k16.row.col.f32.f16.f16.f32 "
        "{%0,%1,%2,%3}, {%4,%5,%6,%7}, {%8,%9}, {%0,%1,%2,%3};"
        : "+f"(d[0]),"+f"(d[1]),"+f"(d[2]),"+f"(d[3])
        : "r"(a0),"r"(a1),"r"(a2),"r"(a3),"r"(b0),"r"(b1));
}
__device__ __forceinline__ u32 h2u(__half2 h){ return *(u32*)&h; }

// ---- scratch globals ----
__device__ float g_M1[10], g_M2[55], g_w1p[1280], g_c1[128];
__device__ float g_sum2[64], g_sumsq2[64], g_a2[64], g_c2[64];

__global__ void k_zero(){
    int t = threadIdx.x;
    if (t < 10) g_M1[t]=0.f;
    if (t < 55) g_M2[t]=0.f;
    if (t < 64){ g_sum2[t]=0.f; g_sumsq2[t]=0.f; }
}

// ---- K1: concat moments, center-factored ----
__global__ void k_stats(const float* __restrict__ p){
    __shared__ float red[8][65];
    float m1[10], m2[55];
#pragma unroll
    for (int i=0;i<10;i++) m1[i]=0.f;
#pragma unroll
    for (int i=0;i<55;i++) m2[i]=0.f;

    int n = blockIdx.x*blockDim.x + threadIdx.x;
    {
        float4 pr[12];
        const float4* pp = (const float4*)(p + (size_t)n*48);
#pragma unroll
        for (int i=0;i<12;i++) pr[i] = pp[i];
        const float* pc = (const float*)pr;
        float C0=pc[0], C1=pc[1], C2=pc[2];
        float Sq0=0.f,Sq1=0.f,Sq2=0.f;
        float Q00=0.f,Q01=0.f,Q02=0.f,Q11=0.f,Q12=0.f,Q22=0.f;
        float Sd=0.f, Sdq0=0.f,Sdq1=0.f,Sdq2=0.f, Sdd=0.f;
#pragma unroll
        for (int k=0;k<16;k++){
            float qx=pc[3*k], qy=pc[3*k+1], qz=pc[3*k+2];
            float dx=C0-qx, dy=C1-qy, dz=C2-qz;
            float d2 = dx*dx + dy*dy + dz*dz;
            float ds = sqrtf(d2);
            Sq0+=qx; Sq1+=qy; Sq2+=qz;
            Q00=fmaf(qx,qx,Q00); Q01=fmaf(qx,qy,Q01); Q02=fmaf(qx,qz,Q02);
            Q11=fmaf(qy,qy,Q11); Q12=fmaf(qy,qz,Q12); Q22=fmaf(qz,qz,Q22);
            Sd+=ds; Sdq0=fmaf(ds,qx,Sdq0); Sdq1=fmaf(ds,qy,Sdq1); Sdq2=fmaf(ds,qz,Sdq2);
            Sdd+=d2;
        }
        float C[3]={C0,C1,C2};
        float Sq[3]={Sq0,Sq1,Sq2};
        float QQ[3][3]={{Q00,Q01,Q02},{Q01,Q11,Q12},{Q02,Q12,Q22}};
        float SDQ[3]={Sdq0,Sdq1,Sdq2};
#pragma unroll
        for (int i=0;i<3;i++){
            m1[i]   += 16.f*C[i];
            m1[3+i] += Sq[i];
            m1[6+i] += 16.f*C[i]-Sq[i];
        }
        m1[9] += Sd;
        int t = 0;
#pragma unroll
        for (int a=0;a<3;a++){
#pragma unroll
            for (int b=a;b<3;b++) m2[t++] += 16.f*C[a]*C[b];
#pragma unroll
            for (int b=0;b<3;b++) m2[t++] += C[a]*Sq[b];
#pragma unroll
            for (int b=0;b<3;b++) m2[t++] += C[a]*(16.f*C[b]-Sq[b]);
            m2[t++] += C[a]*Sd;
        }
#pragma unroll
        for (int a=0;a<3;a++){
#pragma unroll
            for (int b=a;b<3;b++) m2[t++] += QQ[a][b];
#pragma unroll
            for (int b=0;b<3;b++) m2[t++] += C[b]*Sq[a]-QQ[a][b];
            m2[t++] += SDQ[a];
        }
#pragma unroll
        for (int a=0;a<3;a++){
#pragma unroll
            for (int b=a;b<3;b++)
                m2[t++] += 16.f*C[a]*C[b]-C[a]*Sq[b]-C[b]*Sq[a]+QQ[a][b];
            m2[t++] += C[a]*Sd - SDQ[a];
        }
        m2[t++] += Sdd;
    }
#pragma unroll
    for (int off=16; off>0; off>>=1){
#pragma unroll
        for (int i=0;i<10;i++) m1[i] += __shfl_down_sync(0xffffffffu, m1[i], off);
#pragma unroll
        for (int i=0;i<55;i++) m2[i] += __shfl_down_sync(0xffffffffu, m2[i], off);
    }
    int wid = threadIdx.x>>5;
    if ((threadIdx.x&31)==0){
#pragma unroll
        for (int i=0;i<10;i++) red[wid][i]=m1[i];
#pragma unroll
        for (int i=0;i<55;i++) red[wid][10+i]=m2[i];
    }
    __syncthreads();
    if (threadIdx.x < 65){
        float a=0.f;
#pragma unroll
        for (int w=0;w<8;w++) a += red[w][threadIdx.x];
        if (threadIdx.x < 10) atomicAdd(&g_M1[threadIdx.x], a);
        else atomicAdd(&g_M2[threadIdx.x-10], a);
    }
}

__global__ void k_fold(const float* __restrict__ w1, const float* __restrict__ g1,
                       const float* __restrict__ be1){
    int d = threadIdx.x;
    const double invNK = 1.0/(double)NK;
    double wv[10];
#pragma unroll
    for (int c=0;c<10;c++) wv[c] = (double)w1[c*128+d];
    double m = 0.0;
#pragma unroll
    for (int c=0;c<10;c++) m += ((double)g_M1[c]*invNK)*wv[c];
    double q = 0.0; int t = 0;
#pragma unroll
    for (int a=0;a<10;a++)
#pragma unroll
        for (int b=a;b<10;b++){
            double s2 = (double)g_M2[t++]*invNK;
            double term = s2*wv[a]*wv[b];
            q += (a==b) ? term : 2.0*term;
        }
    double var = q - m*m;
    double a1 = (double)g1[d] / sqrt(var + 1e-5);
    g_c1[d] = (float)((double)be1[d] - m*a1);
#pragma unroll
    for (int c=0;c<10;c++) g_w1p[c*128+d] = (float)(wv[c]*a1);
}

__device__ __forceinline__ float w8row(int r, int c){
    switch(r){
        case 0: return g_w1p[384+c] - g_w1p[768+c];
        case 1: return g_w1p[512+c] - g_w1p[896+c];
        case 2: return g_w1p[640+c] - g_w1p[1024+c];
        case 3: return g_w1p[1152+c];
        case 4: return g_w1p[c]     + g_w1p[768+c];
        case 5: return g_w1p[128+c] + g_w1p[896+c];
        case 6: return g_w1p[256+c] + g_w1p[1024+c];
        default: return g_c1[c];
    }
}

__global__ void __launch_bounds__(NT,1) k_main(
    const float* __restrict__ p, const float* __restrict__ x,
    const float* __restrict__ w2, const float* __restrict__ b2,
    const float* __restrict__ ws, const float* __restrict__ wo,
    const float* __restrict__ bo, float* __restrict__ out)
{
    extern __shared__ float sm[];
    __half* acth  = (__half*)sm;                 // 128 x 136
    __half* feath = (__half*)(sm + F_FEAT);      // 16 x 136
    int tid = threadIdx.x, w = tid>>5, lid = tid&31;
    int g = lid>>2, tq = lid&3;
    int wl = w & 7;
    int rA = wl*16;
    bool lowhalf = (w < 8);
    int rg = w & 3, cg = w >> 2;
    int row0 = rg*32;

    // ---- stage fp16 weight fragments ----
    for (int i = tid; i < 1024; i += NT){          // w2: [K8][np4][lane] float4
        int lane = i&31, j = (i>>5)&3, K = i>>7;
        int g2 = lane>>2, t2 = lane&3;
        int r0 = K*16 + 2*t2;
        int c0 = (2*j)*8 + g2, c1 = (2*j+1)*8 + g2;
        uint4 v;
        v.x = h2u(__floats2half2_rn(w2[r0*64+c0],     w2[(r0+1)*64+c0]));
        v.y = h2u(__floats2half2_rn(w2[(r0+8)*64+c0], w2[(r0+9)*64+c0]));
        v.z = h2u(__floats2half2_rn(w2[r0*64+c1],     w2[(r0+1)*64+c1]));
        v.w = h2u(__floats2half2_rn(w2[(r0+8)*64+c1], w2[(r0+9)*64+c1]));
        *(uint4*)&sm[F_W2F + i*4] = v;
    }
    for (int i = tid; i < 2048; i += NT){          // ws: [K8][np8][lane] float4
        int lane = i&31, j = (i>>5)&7, K = i>>8;
        int g2 = lane>>2, t2 = lane&3;
        int r0 = K*16 + 2*t2;
        int c0 = (2*j)*8 + g2, c1 = (2*j+1)*8 + g2;
        uint4 v;
        v.x = h2u(__floats2half2_rn(ws[r0*128+c0],     ws[(r0+1)*128+c0]));
        v.y = h2u(__floats2half2_rn(ws[(r0+8)*128+c0], ws[(r0+9)*128+c0]));
        v.z = h2u(__floats2half2_rn(ws[r0*128+c1],     ws[(r0+1)*128+c1]));
        v.w = h2u(__floats2half2_rn(ws[(r0+8)*128+c1], ws[(r0+9)*128+c1]));
        *(uint4*)&sm[F_WSF + i*4] = v;
    }
    for (int i = tid; i < 2048; i += NT){          // wo: [K8][n8][lane] float2
        int lane = i&31, n = (i>>5)&7, K = i>>8;
        int g2 = lane>>2, t2 = lane&3;
        int r0 = K*16 + 2*t2, c = n*8 + g2;
        uint2 v;
        v.x = h2u(__floats2half2_rn(wo[r0*64+c],     wo[(r0+1)*64+c]));
        v.y = h2u(__floats2half2_rn(wo[(r0+8)*64+c], wo[(r0+9)*64+c]));
        *(uint2*)&sm[F_WOF + i*2] = v;
    }
    if (tid < 256){                                // layer1 B frags (tf32 hi/lo)
        int i = tid, l2 = i&31, n2 = (i>>5)&7;
        int g2 = l2>>2, t2 = l2&3;
#pragma unroll
        for (int j=0;j<2;j++){
            int c = (2*n2+j)*8 + g2;
            float v0 = w8row(t2,   c);
            float v1 = w8row(t2+4, c);
            float h0 = to_tf32(v0), h1 = to_tf32(v1);
            sm[F_W1FH + (n2*32+l2)*4 + 2*j  ] = h0;
            sm[F_W1FH + (n2*32+l2)*4 + 2*j+1] = h1;
            sm[F_W1FL + (n2*32+l2)*4 + 2*j  ] = to_tf32(v0-h0);
            sm[F_W1FL + (n2*32+l2)*4 + 2*j+1] = to_tf32(v1-h1);
        }
    }
    if (tid < 64){ sm[F_B2+tid]=b2[tid]; sm[F_BO+tid]=bo[tid]; sm[F_BNS+tid]=0.f; sm[F_BNQ+tid]=0.f; }
    __syncthreads();

    float bs0=0.f, bs1=0.f, bq0=0.f, bq1=0.f;
    int xrow = wl*16 + (lid>>1);
    int xcol = (lowhalf?0:32) + (lid&1)*16;
    int half_ = 0, tprev = 0;

    for (int t = blockIdx.x; t < NTILES; t += gridDim.x){
        // prefetch x, convert to fp16 pairs
        const float4* xp = (const float4*)(x + ((size_t)t*128 + xrow)*64 + xcol);
        u32 xh[8];
#pragma unroll
        for (int i=0;i<4;i++){
            float4 v = xp[i];
            xh[2*i]   = h2u(__floats2half2_rn(v.x, v.y));
            xh[2*i+1] = h2u(__floats2half2_rn(v.z, v.w));
        }

        // build layer1 A (hi/lo) straight from global p
        if (tid < 128){
            int pt = tid>>4, k = tid&15;
            const float* pb = p + (size_t)t*384 + pt*48;
            float cx=pb[0], cy=pb[1], cz=pb[2];
            float qx=pb[3*k], qy=pb[3*k+1], qz=pb[3*k+2];
            float dx=cx-qx, dy=cy-qy, dz=cz-qz;
            float ds = sqrtf(dx*dx+dy*dy+dz*dz);
            float vv[8] = {qx,qy,qz,ds,cx,cy,cz,1.f};
#pragma unroll
            for (int c=0;c<8;c++){
                float hi = to_tf32(vv[c]);
                sm[F_A1H + tid*12 + c] = hi;
                sm[F_A1L + tid*12 + c] = to_tf32(vv[c]-hi);
            }
        }
        __syncthreads();

        // ---- GEMM1 (K=8, split tf32): h = relu(A1 @ W8) -> ACT fp16 ----
        {
            u32 ah0 = __float_as_uint(sm[F_A1H + (rA+g  )*12 + tq]);
            u32 ah1 = __float_as_uint(sm[F_A1H + (rA+g+8)*12 + tq]);
            u32 ah2 = __float_as_uint(sm[F_A1H + (rA+g  )*12 + tq+4]);
            u32 ah3 = __float_as_uint(sm[F_A1H + (rA+g+8)*12 + tq+4]);
            u32 al0 = __float_as_uint(sm[F_A1L + (rA+g  )*12 + tq]);
            u32 al1 = __float_as_uint(sm[F_A1L + (rA+g+8)*12 + tq]);
            u32 al2 = __float_as_uint(sm[F_A1L + (rA+g  )*12 + tq+4]);
            u32 al3 = __float_as_uint(sm[F_A1L + (rA+g+8)*12 + tq+4]);
            int n2b = lowhalf ? 0 : 4;
#pragma unroll
            for (int j=0;j<4;j++){
                int n2g = n2b + j;
                float4 bh = *(float4*)&sm[F_W1FH + (n2g*32+lid)*4];
                float4 bl = *(float4*)&sm[F_W1FL + (n2g*32+lid)*4];
#pragma unroll
                for (int par=0;par<2;par++){
                    float d[4] = {0.f,0.f,0.f,0.f};
                    u32 b0 = __float_as_uint(par? bh.z : bh.x);
                    u32 b1 = __float_as_uint(par? bh.w : bh.y);
                    u32 c0u= __float_as_uint(par? bl.z : bl.x);
                    u32 c1u= __float_as_uint(par? bl.w : bl.y);
                    mma4(d, ah0,ah1,ah2,ah3, b0,b1);
                    mma4(d, al0,al1,al2,al3, b0,b1);
                    mma4(d, ah0,ah1,ah2,ah3, c0u,c1u);
                    int c0 = (n2g*2+par)*8 + 2*tq;
                    *(u32*)(acth + (rA+g  )*136 + c0) =
                        h2u(__floats2half2_rn(fmaxf(d[0],0.f), fmaxf(d[1],0.f)));
                    *(u32*)(acth + (rA+g+8)*136 + c0) =
                        h2u(__floats2half2_rn(fmaxf(d[2],0.f), fmaxf(d[3],0.f)));
                }
            }
        }
        __syncthreads();

        // ---- GEMM2: p_c = h @ w2 (fp16 k16, K=8 steps, 4 n-tiles/warp) ----
        float d2[4][4];
#pragma unroll
        for (int n=0;n<4;n++){ d2[n][0]=0.f; d2[n][1]=0.f; d2[n][2]=0.f; d2[n][3]=0.f; }
        {
            int n2b = lowhalf ? 0 : 2;
#pragma unroll
            for (int K=0;K<8;K++){
                const __half* ar = acth + K*16 + 2*tq;
                u32 a0 = *(u32*)(ar + (rA+g  )*136);
                u32 a1 = *(u32*)(ar + (rA+g+8)*136);
                u32 a2 = *(u32*)(ar + (rA+g  )*136 + 8);
                u32 a3 = *(u32*)(ar + (rA+g+8)*136 + 8);
                float4 bA = *(float4*)&sm[F_W2F + ((K*4+n2b  )*32+lid)*4];
                float4 bB = *(float4*)&sm[F_W2F + ((K*4+n2b+1)*32+lid)*4];
                mma16(d2[0], a0,a1,a2,a3, __float_as_uint(bA.x), __float_as_uint(bA.y));
                mma16(d2[1], a0,a1,a2,a3, __float_as_uint(bA.z), __float_as_uint(bA.w));
                mma16(d2[2], a0,a1,a2,a3, __float_as_uint(bB.x), __float_as_uint(bB.y));
                mma16(d2[3], a0,a1,a2,a3, __float_as_uint(bB.z), __float_as_uint(bB.w));
            }
        }
        // write px = [p_c + b2 | x] (fp16)
        {
            int nb = lowhalf ? 0 : 4;
#pragma unroll
            for (int n=0;n<4;n++){
                int c0 = (nb+n)*8 + 2*tq;
                float ba = sm[F_B2+c0], bb2 = sm[F_B2+c0+1];
                *(u32*)(acth + (rA+g  )*136 + c0) =
                    h2u(__floats2half2_rn(d2[n][0]+ba, d2[n][1]+bb2));
                *(u32*)(acth + (rA+g+8)*136 + c0) =
                    h2u(__floats2half2_rn(d2[n][2]+ba, d2[n][3]+bb2));
            }
#pragma unroll
            for (int i=0;i<4;i++)
                *(uint2*)(acth + xrow*136 + 64 + xcol + i*4) = *(uint2*)&xh[2*i];
        }
        __syncthreads();

        // ---- GEMM3: logits = px @ ws (fp16 k16, mt=2, nt=4) ----
        float d3[2][4][4];
#pragma unroll
        for (int m=0;m<2;m++)
#pragma unroll
            for (int n=0;n<4;n++){ d3[m][n][0]=0.f; d3[m][n][1]=0.f; d3[m][n][2]=0.f; d3[m][n][3]=0.f; }
        {
#pragma unroll
            for (int K=0;K<8;K++){
                const __half* ar = acth + K*16 + 2*tq;
                u32 a[2][4];
#pragma unroll
                for (int m=0;m<2;m++){
                    int rb = row0 + m*16;
                    a[m][0] = *(u32*)(ar + (rb+g  )*136);
                    a[m][1] = *(u32*)(ar + (rb+g+8)*136);
                    a[m][2] = *(u32*)(ar + (rb+g  )*136 + 8);
                    a[m][3] = *(u32*)(ar + (rb+g+8)*136 + 8);
                }
                float4 bA = *(float4*)&sm[F_WSF + ((K*8 + 2*cg  )*32+lid)*4];
                float4 bB = *(float4*)&sm[F_WSF + ((K*8 + 2*cg+1)*32+lid)*4];
#pragma unroll
                for (int m=0;m<2;m++){
                    mma16(d3[m][0], a[m][0],a[m][1],a[m][2],a[m][3], __float_as_uint(bA.x), __float_as_uint(bA.y));
                    mma16(d3[m][1], a[m][0],a[m][1],a[m][2],a[m][3], __float_as_uint(bA.z), __float_as_uint(bA.w));
                    mma16(d3[m][2], a[m][0],a[m][1],a[m][2],a[m][3], __float_as_uint(bB.x), __float_as_uint(bB.y));
                    mma16(d3[m][3], a[m][0],a[m][1],a[m][2],a[m][3], __float_as_uint(bB.z), __float_as_uint(bB.w));
                }
            }
        }

        // ---- softmax over k + pooled feat -> FEAT rows [half_*8 ..] ----
        {
            int fbase = half_*8;
#pragma unroll
            for (int m=0;m<2;m++){
                int pt = 2*rg + m;
                int rb = row0 + m*16;
#pragma unroll
                for (int nl=0; nl<4; nl++){
                    int c0 = (4*cg+nl)*8 + 2*tq;
                    float e0 = __expf(d3[m][nl][0]), e1 = __expf(d3[m][nl][1]);
                    float e2 = __expf(d3[m][nl][2]), e3 = __expf(d3[m][nl][3]);
                    float2 plo = __half22float2(*(__half2*)(acth + (rb+g  )*136 + c0));
                    float2 phi = __half22float2(*(__half2*)(acth + (rb+g+8)*136 + c0));
                    float se = e0+e2, so_ = e1+e3;
                    float ve = fmaf(e0, plo.x, e2*phi.x);
                    float vo = fmaf(e1, plo.y, e3*phi.y);
#pragma unroll
                    for (int mm=4;mm<32;mm<<=1){
                        se += __shfl_xor_sync(0xffffffffu, se, mm);
                        so_ += __shfl_xor_sync(0xffffffffu, so_, mm);
                        ve += __shfl_xor_sync(0xffffffffu, ve, mm);
                        vo += __shfl_xor_sync(0xffffffffu, vo, mm);
                    }
                    if (lid < 4)
                        *(u32*)(feath + (fbase+pt)*136 + c0) =
                            h2u(__floats2half2_rn(ve/se, vo/so_));
                }
            }
        }

        if (half_ == 0){
            tprev = t; half_ = 1;
            __syncthreads();
        } else {
            __syncthreads();
            // ---- paired epilogue: 16 FEAT rows @ wo (fp16 k16) ----
            if (lowhalf){
                float d[4] = {0.f,0.f,0.f,0.f};
#pragma unroll
                for (int K=0;K<8;K++){
                    const __half* ar = feath + K*16 + 2*tq;
                    u32 a0 = *(u32*)(ar + g*136);
                    u32 a1 = *(u32*)(ar + (g+8)*136);
                    u32 a2 = *(u32*)(ar + g*136 + 8);
                    u32 a3 = *(u32*)(ar + (g+8)*136 + 8);
                    uint2 bv = *(uint2*)&sm[F_WOF + ((K*8+w)*32+lid)*2];
                    mma16(d, a0,a1,a2,a3, bv.x, bv.y);
                }
                int c0 = w*8 + 2*tq;
                float ba = sm[F_BO+c0], bb = sm[F_BO+c0+1];
                float v0 = d[0]+ba, v1 = d[1]+bb;   // FEAT row g   -> tprev point g
                float v2 = d[2]+ba, v3 = d[3]+bb;   // FEAT row g+8 -> t     point g
                float2 va; va.x=v0; va.y=v1;
                float2 vb; vb.x=v2; vb.y=v3;
                *(float2*)&out[((size_t)tprev*8 + g)*64 + c0] = va;
                *(float2*)&out[((size_t)t*8     + g)*64 + c0] = vb;
                bs0 += v0+v2; bq0 += fmaf(v0,v0,v2*v2);
                bs1 += v1+v3; bq1 += fmaf(v1,v1,v3*v3);
            }
            half_ = 0;
        }
    }

    // ---- tail: one unpaired tile left in FEAT rows 0-7 ----
    if (half_ && lowhalf){
        float d[4] = {0.f,0.f,0.f,0.f};
#pragma unroll
        for (int K=0;K<8;K++){
            const __half* ar = feath + K*16 + 2*tq;
            u32 a0 = *(u32*)(ar + g*136);
            u32 a1 = *(u32*)(ar + (g+8)*136);   // stale rows, unused
            u32 a2 = *(u32*)(ar + g*136 + 8);
            u32 a3 = *(u32*)(ar + (g+8)*136 + 8);
            uint2 bv = *(uint2*)&sm[F_WOF + ((K*8+w)*32+lid)*2];
            mma16(d, a0,a1,a2,a3, bv.x, bv.y);
        }
        int c0 = w*8 + 2*tq;
        float ba = sm[F_BO+c0], bb = sm[F_BO+c0+1];
        float v0 = d[0]+ba, v1 = d[1]+bb;
        float2 va; va.x=v0; va.y=v1;
        *(float2*)&out[((size_t)tprev*8 + g)*64 + c0] = va;
        bs0 += v0; bq0 += v0*v0;
        bs1 += v1; bq1 += v1*v1;
    }

    if (lowhalf){
        int c0 = w*8 + 2*tq;
        atomicAdd(&sm[F_BNS+c0  ], bs0);
        atomicAdd(&sm[F_BNS+c0+1], bs1);
        atomicAdd(&sm[F_BNQ+c0  ], bq0);
        atomicAdd(&sm[F_BNQ+c0+1], bq1);
    }
    __syncthreads();
    if (tid < 64){
        atomicAdd(&g_sum2[tid],   sm[F_BNS+tid]);
        atomicAdd(&g_sumsq2[tid], sm[F_BNQ+tid]);
    }
}

__global__ void k_fin(const float* __restrict__ g2, const float* __restrict__ be2){
    int j = threadIdx.x;
    double inv = 1.0/(double)Nn;
    double mu  = (double)g_sum2[j]*inv;
    double var = (double)g_sumsq2[j]*inv - mu*mu;
    double a2  = (double)g2[j] / sqrt(var + 1e-5);
    g_a2[j] = (float)a2;
    g_c2[j] = (float)((double)be2[j] - mu*a2);
}

__global__ void k_norm(float* __restrict__ out){
    __shared__ float a2s[64], c2s[64];
    if (threadIdx.x < 64){ a2s[threadIdx.x]=g_a2[threadIdx.x]; c2s[threadIdx.x]=g_c2[threadIdx.x]; }
    __syncthreads();
    const int nq = Nn*64/4;
    float4* o4 = (float4*)out;
    for (int f = blockIdx.x*blockDim.x + threadIdx.x; f < nq; f += gridDim.x*blockDim.x){
        float4 v = o4[f];
        int j = (f*4) & 63;
        v.x = fmaxf(fmaf(v.x, a2s[j],   c2s[j]),   0.f);
        v.y = fmaxf(fmaf(v.y, a2s[j+1], c2s[j+1]), 0.f);
        v.z = fmaxf(fmaf(v.z, a2s[j+2], c2s[j+2]), 0.f);
        v.w = fmaxf(fmaf(v.w, a2s[j+3], c2s[j+3]), 0.f);
        o4[f] = v;
    }
}

extern "C" void kernel_launch(void* const* d_in, const int* in_sizes, int n_in,
                              void* d_out, int out_size){
    const float* p   = (const float*)d_in[0];
    const float* x   = (const float*)d_in[1];
    const float* w1  = (const float*)d_in[2];
    const float* g1  = (const float*)d_in[4];
    const float* be1 = (const float*)d_in[5];
    const float* w2  = (const float*)d_in[6];
    const float* b2  = (const float*)d_in[7];
    const float* ws  = (const float*)d_in[8];
    const float* wo  = (const float*)d_in[9];
    const float* bo  = (const float*)d_in[10];
    const float* g2  = (const float*)d_in[11];
    const float* be2 = (const float*)d_in[12];
    float* out = (float*)d_out;
    (void)in_sizes; (void)n_in; (void)out_size;

    cudaFuncSetAttribute(k_main, cudaFuncAttributeMaxDynamicSharedMemorySize, SMEM_BYTES);

    k_zero<<<1,64>>>();
    k_stats<<<256,256>>>(p);
    k_fold<<<1,128>>>(w1,g1,be1);
    k_main<<<GRID_MAIN,NT,SMEM_BYTES>>>(p,x,w2,b2,ws,wo,bo,out);
    k_fin<<<1,64>>>(g2,be2);
    k_norm<<<2048,256>>>(out);
}

// round 14
// speedup vs baseline: 2.3677x; 1.0840x over previous
#include <cuda_runtime.h>
#include <cuda_fp16.h>
typedef unsigned int u32;

#define Nn 65536
#define NK (Nn*16)
#define NTILES (Nn/8)
#define NT 512
#define GRID_MAIN 148

// ---- k_main float offsets in dynamic smem ----
#define F_ACT   0          // halves: 128 x 136 = 8704 floats
#define F_W1FH  8704       // 1024
#define F_W1FL  9728       // 1024
#define F_W2F   10752      // 4096
#define F_WSF   14848      // 8192
#define F_WOF   23040      // 4096
#define F_FEAT  27136      // halves: 16 x 136 = 1088 floats
#define F_B2    28224
#define F_BO    28288
#define F_BNS   28352
#define F_BNQ   28416
#define F_TOTAL 28480
#define SMEM_BYTES (F_TOTAL*4)

__device__ __forceinline__ float to_tf32(float x){
    float r; asm("cvt.rna.tf32.f32 %0, %1;":"=f"(r):"f"(x)); return r;
}
__device__ __forceinline__ void mma4(float* d, u32 a0, u32 a1, u32 a2, u32 a3,
                                     u32 b0, u32 b1){
    asm volatile("mma.sync.aligned.m16n8k8.row.col.f32.tf32.tf32.f32 "
        "{%0,%1,%2,%3}, {%4,%5,%6,%7}, {%8,%9}, {%0,%1,%2,%3};"
        : "+f"(d[0]),"+f"(d[1]),"+f"(d[2]),"+f"(d[3])
        : "r"(a0),"r"(a1),"r"(a2),"r"(a3),"r"(b0),"r"(b1));
}
__device__ __forceinline__ void mma16(float* d, u32 a0, u32 a1, u32 a2, u32 a3,
                                      u32 b0, u32 b1){
    asm volatile("mma.sync.aligned.m16n8k16.row.col.f32.f16.f16.f32 "
        "{%0,%1,%2,%3}, {%4,%5,%6,%7}, {%8,%9}, {%0,%1,%2,%3};"
        : "+f"(d[0]),"+f"(d[1]),"+f"(d[2]),"+f"(d[3])
        : "r"(a0),"r"(a1),"r"(a2),"r"(a3),"r"(b0),"r"(b1));
}
__device__ __forceinline__ u32 h2u(__half2 h){ return *(u32*)&h; }
__device__ __forceinline__ u32 cvta_sh(const void* p){
    u32 a; asm("{ .reg .u64 t; cvta.to.shared.u64 t, %1; cvt.u32.u64 %0, t; }":"=r"(a):"l"(p)); return a;
}
#define LDM4(r0,r1,r2,r3,addr) \
    asm volatile("ldmatrix.sync.aligned.m8n8.x4.shared.b16 {%0,%1,%2,%3}, [%4];" \
        : "=r"(r0),"=r"(r1),"=r"(r2),"=r"(r3) : "r"(addr))
#define STM4(addr,r0,r1,r2,r3) \
    asm volatile("stmatrix.sync.aligned.m8n8.x4.shared.b16 [%0], {%1,%2,%3,%4};" \
        :: "r"(addr),"r"(r0),"r"(r1),"r"(r2),"r"(r3))

// ---- scratch globals ----
__device__ float g_M1[10], g_M2[55], g_w1p[1280], g_c1[128];
__device__ float g_sum2[64], g_sumsq2[64], g_a2[64], g_c2[64];

__global__ void k_zero(){
    int t = threadIdx.x;
    if (t < 10) g_M1[t]=0.f;
    if (t < 55) g_M2[t]=0.f;
    if (t < 64){ g_sum2[t]=0.f; g_sumsq2[t]=0.f; }
}

// ---- K1: concat moments, center-factored ----
__global__ void k_stats(const float* __restrict__ p){
    __shared__ float red[8][65];
    float m1[10], m2[55];
#pragma unroll
    for (int i=0;i<10;i++) m1[i]=0.f;
#pragma unroll
    for (int i=0;i<55;i++) m2[i]=0.f;

    int n = blockIdx.x*blockDim.x + threadIdx.x;
    {
        float4 pr[12];
        const float4* pp = (const float4*)(p + (size_t)n*48);
#pragma unroll
        for (int i=0;i<12;i++) pr[i] = pp[i];
        const float* pc = (const float*)pr;
        float C0=pc[0], C1=pc[1], C2=pc[2];
        float Sq0=0.f,Sq1=0.f,Sq2=0.f;
        float Q00=0.f,Q01=0.f,Q02=0.f,Q11=0.f,Q12=0.f,Q22=0.f;
        float Sd=0.f, Sdq0=0.f,Sdq1=0.f,Sdq2=0.f, Sdd=0.f;
#pragma unroll
        for (int k=0;k<16;k++){
            float qx=pc[3*k], qy=pc[3*k+1], qz=pc[3*k+2];
            float dx=C0-qx, dy=C1-qy, dz=C2-qz;
            float d2 = dx*dx + dy*dy + dz*dz;
            float ds = sqrtf(d2);
            Sq0+=qx; Sq1+=qy; Sq2+=qz;
            Q00=fmaf(qx,qx,Q00); Q01=fmaf(qx,qy,Q01); Q02=fmaf(qx,qz,Q02);
            Q11=fmaf(qy,qy,Q11); Q12=fmaf(qy,qz,Q12); Q22=fmaf(qz,qz,Q22);
            Sd+=ds; Sdq0=fmaf(ds,qx,Sdq0); Sdq1=fmaf(ds,qy,Sdq1); Sdq2=fmaf(ds,qz,Sdq2);
            Sdd+=d2;
        }
        float C[3]={C0,C1,C2};
        float Sq[3]={Sq0,Sq1,Sq2};
        float QQ[3][3]={{Q00,Q01,Q02},{Q01,Q11,Q12},{Q02,Q12,Q22}};
        float SDQ[3]={Sdq0,Sdq1,Sdq2};
#pragma unroll
        for (int i=0;i<3;i++){
            m1[i]   += 16.f*C[i];
            m1[3+i] += Sq[i];
            m1[6+i] += 16.f*C[i]-Sq[i];
        }
        m1[9] += Sd;
        int t = 0;
#pragma unroll
        for (int a=0;a<3;a++){
#pragma unroll
            for (int b=a;b<3;b++) m2[t++] += 16.f*C[a]*C[b];
#pragma unroll
            for (int b=0;b<3;b++) m2[t++] += C[a]*Sq[b];
#pragma unroll
            for (int b=0;b<3;b++) m2[t++] += C[a]*(16.f*C[b]-Sq[b]);
            m2[t++] += C[a]*Sd;
        }
#pragma unroll
        for (int a=0;a<3;a++){
#pragma unroll
            for (int b=a;b<3;b++) m2[t++] += QQ[a][b];
#pragma unroll
            for (int b=0;b<3;b++) m2[t++] += C[b]*Sq[a]-QQ[a][b];
            m2[t++] += SDQ[a];
        }
#pragma unroll
        for (int a=0;a<3;a++){
#pragma unroll
            for (int b=a;b<3;b++)
                m2[t++] += 16.f*C[a]*C[b]-C[a]*Sq[b]-C[b]*Sq[a]+QQ[a][b];
            m2[t++] += C[a]*Sd - SDQ[a];
        }
        m2[t++] += Sdd;
    }
#pragma unroll
    for (int off=16; off>0; off>>=1){
#pragma unroll
        for (int i=0;i<10;i++) m1[i] += __shfl_down_sync(0xffffffffu, m1[i], off);
#pragma unroll
        for (int i=0;i<55;i++) m2[i] += __shfl_down_sync(0xffffffffu, m2[i], off);
    }
    int wid = threadIdx.x>>5;
    if ((threadIdx.x&31)==0){
#pragma unroll
        for (int i=0;i<10;i++) red[wid][i]=m1[i];
#pragma unroll
        for (int i=0;i<55;i++) red[wid][10+i]=m2[i];
    }
    __syncthreads();
    if (threadIdx.x < 65){
        float a=0.f;
#pragma unroll
        for (int w=0;w<8;w++) a += red[w][threadIdx.x];
        if (threadIdx.x < 10) atomicAdd(&g_M1[threadIdx.x], a);
        else atomicAdd(&g_M2[threadIdx.x-10], a);
    }
}

__global__ void k_fold(const float* __restrict__ w1, const float* __restrict__ g1,
                       const float* __restrict__ be1){
    int d = threadIdx.x;
    const double invNK = 1.0/(double)NK;
    double wv[10];
#pragma unroll
    for (int c=0;c<10;c++) wv[c] = (double)w1[c*128+d];
    double m = 0.0;
#pragma unroll
    for (int c=0;c<10;c++) m += ((double)g_M1[c]*invNK)*wv[c];
    double q = 0.0; int t = 0;
#pragma unroll
    for (int a=0;a<10;a++)
#pragma unroll
        for (int b=a;b<10;b++){
            double s2 = (double)g_M2[t++]*invNK;
            double term = s2*wv[a]*wv[b];
            q += (a==b) ? term : 2.0*term;
        }
    double var = q - m*m;
    double a1 = (double)g1[d] / sqrt(var + 1e-5);
    g_c1[d] = (float)((double)be1[d] - m*a1);
#pragma unroll
    for (int c=0;c<10;c++) g_w1p[c*128+d] = (float)(wv[c]*a1);
}

__device__ __forceinline__ float w8row(int r, int c){
    switch(r){
        case 0: return g_w1p[384+c] - g_w1p[768+c];
        case 1: return g_w1p[512+c] - g_w1p[896+c];
        case 2: return g_w1p[640+c] - g_w1p[1024+c];
        case 3: return g_w1p[1152+c];
        case 4: return g_w1p[c]     + g_w1p[768+c];
        case 5: return g_w1p[128+c] + g_w1p[896+c];
        case 6: return g_w1p[256+c] + g_w1p[1024+c];
        default: return g_c1[c];
    }
}

__global__ void __launch_bounds__(NT,1) k_main(
    const float* __restrict__ p, const float* __restrict__ x,
    const float* __restrict__ w2, const float* __restrict__ b2,
    const float* __restrict__ ws, const float* __restrict__ wo,
    const float* __restrict__ bo, float* __restrict__ out)
{
    extern __shared__ float sm[];
    __half* acth  = (__half*)sm;                 // 128 x 136
    __half* feath = (__half*)(sm + F_FEAT);      // 16 x 136
    int tid = threadIdx.x, w = tid>>5, lid = tid&31;
    int g = lid>>2, tq = lid&3;
    int wl = w & 7;
    int rA = wl*16;
    bool lowhalf = (w < 8);
    int rg = w & 3, cg = w >> 2;
    int row0 = rg*32;

    // ---- stage fp16 weight fragments ----
    for (int i = tid; i < 1024; i += NT){          // w2
        int lane = i&31, j = (i>>5)&3, K = i>>7;
        int g2 = lane>>2, t2 = lane&3;
        int r0 = K*16 + 2*t2;
        int c0 = (2*j)*8 + g2, c1 = (2*j+1)*8 + g2;
        uint4 v;
        v.x = h2u(__floats2half2_rn(w2[r0*64+c0],     w2[(r0+1)*64+c0]));
        v.y = h2u(__floats2half2_rn(w2[(r0+8)*64+c0], w2[(r0+9)*64+c0]));
        v.z = h2u(__floats2half2_rn(w2[r0*64+c1],     w2[(r0+1)*64+c1]));
        v.w = h2u(__floats2half2_rn(w2[(r0+8)*64+c1], w2[(r0+9)*64+c1]));
        *(uint4*)&sm[F_W2F + i*4] = v;
    }
    for (int i = tid; i < 2048; i += NT){          // ws
        int lane = i&31, j = (i>>5)&7, K = i>>8;
        int g2 = lane>>2, t2 = lane&3;
        int r0 = K*16 + 2*t2;
        int c0 = (2*j)*8 + g2, c1 = (2*j+1)*8 + g2;
        uint4 v;
        v.x = h2u(__floats2half2_rn(ws[r0*128+c0],     ws[(r0+1)*128+c0]));
        v.y = h2u(__floats2half2_rn(ws[(r0+8)*128+c0], ws[(r0+9)*128+c0]));
        v.z = h2u(__floats2half2_rn(ws[r0*128+c1],     ws[(r0+1)*128+c1]));
        v.w = h2u(__floats2half2_rn(ws[(r0+8)*128+c1], ws[(r0+9)*128+c1]));
        *(uint4*)&sm[F_WSF + i*4] = v;
    }
    for (int i = tid; i < 2048; i += NT){          // wo
        int lane = i&31, n = (i>>5)&7, K = i>>8;
        int g2 = lane>>2, t2 = lane&3;
        int r0 = K*16 + 2*t2, c = n*8 + g2;
        uint2 v;
        v.x = h2u(__floats2half2_rn(wo[r0*64+c],     wo[(r0+1)*64+c]));
        v.y = h2u(__floats2half2_rn(wo[(r0+8)*64+c], wo[(r0+9)*64+c]));
        *(uint2*)&sm[F_WOF + i*2] = v;
    }
    if (tid < 256){                                // layer1 B frags (tf32 hi/lo)
        int i = tid, l2 = i&31, n2 = (i>>5)&7;
        int g2 = l2>>2, t2 = l2&3;
#pragma unroll
        for (int j=0;j<2;j++){
            int c = (2*n2+j)*8 + g2;
            float v0 = w8row(t2,   c);
            float v1 = w8row(t2+4, c);
            float h0 = to_tf32(v0), h1 = to_tf32(v1);
            sm[F_W1FH + (n2*32+l2)*4 + 2*j  ] = h0;
            sm[F_W1FH + (n2*32+l2)*4 + 2*j+1] = h1;
            sm[F_W1FL + (n2*32+l2)*4 + 2*j  ] = to_tf32(v0-h0);
            sm[F_W1FL + (n2*32+l2)*4 + 2*j+1] = to_tf32(v1-h1);
        }
    }
    if (tid < 64){ sm[F_B2+tid]=b2[tid]; sm[F_BO+tid]=bo[tid]; sm[F_BNS+tid]=0.f; sm[F_BNQ+tid]=0.f; }
    __syncthreads();

    u32 smb = cvta_sh(sm);
    u32 fb  = smb + F_FEAT*4;
    u32 lmoff = (u32)((lid&15)*272 + ((lid&16)?16:0));
    u32 actA  = smb + (u32)(rA*272) + lmoff;       // warp's own rows
    u32 base3[2];
    base3[0] = smb + (u32)(row0*272) + lmoff;
    base3[1] = base3[0] + 16*272;

    float bs0=0.f, bs1=0.f, bq0=0.f, bq1=0.f;
    int xrow = wl*16 + (lid>>1);
    int xcol = (lowhalf?0:32) + (lid&1)*16;
    int half_ = 0, tprev = 0;

    for (int t = blockIdx.x; t < NTILES; t += gridDim.x){
        // prefetch x, convert to fp16 pairs
        const float4* xp = (const float4*)(x + ((size_t)t*128 + xrow)*64 + xcol);
        u32 xh[8];
#pragma unroll
        for (int i=0;i<4;i++){
            float4 v = xp[i];
            xh[2*i]   = h2u(__floats2half2_rn(v.x, v.y));
            xh[2*i+1] = h2u(__floats2half2_rn(v.z, v.w));
        }

        // ---- layer-1 A fragments in registers (rows g, g+8 of point wl) ----
        u32 ah0, ah1, ah2, al0, al1, al2;
        {
            const float* pb = p + (size_t)t*384 + wl*48;
            float cxv=pb[0], cyv=pb[1], czv=pb[2];
            float qa0=pb[3*g],    qa1=pb[3*g+1],  qa2=pb[3*g+2];
            float qb0=pb[3*g+24], qb1=pb[3*g+25], qb2=pb[3*g+26];
            float da0=cxv-qa0, da1=cyv-qa1, da2=czv-qa2;
            float db0=cxv-qb0, db1=cyv-qb1, db2=czv-qb2;
            float dsa=sqrtf(da0*da0+da1*da1+da2*da2);
            float dsb=sqrtf(db0*db0+db1*db1+db2*db2);
            float va = (tq==0)?qa0:(tq==1)?qa1:(tq==2)?qa2:dsa;
            float vb = (tq==0)?qb0:(tq==1)?qb1:(tq==2)?qb2:dsb;
            float wa = (tq==0)?cxv:(tq==1)?cyv:(tq==2)?czv:1.f;
            float h0=to_tf32(va), h1=to_tf32(vb), h2=to_tf32(wa);
            ah0=__float_as_uint(h0); al0=__float_as_uint(to_tf32(va-h0));
            ah1=__float_as_uint(h1); al1=__float_as_uint(to_tf32(vb-h1));
            ah2=__float_as_uint(h2); al2=__float_as_uint(to_tf32(wa-h2));
        }

        // ---- GEMM1 (K=8, split tf32): h = relu(A1 @ W8) -> stmatrix ----
        {
            int n2b = lowhalf ? 0 : 4;
#pragma unroll
            for (int j=0;j<4;j++){
                int n2g = n2b + j;
                float4 bh = *(float4*)&sm[F_W1FH + (n2g*32+lid)*4];
                float4 bl = *(float4*)&sm[F_W1FL + (n2g*32+lid)*4];
                float dA[4] = {0.f,0.f,0.f,0.f};
                float dB[4] = {0.f,0.f,0.f,0.f};
                mma4(dA, ah0,ah1,ah2,ah2, __float_as_uint(bh.x), __float_as_uint(bh.y));
                mma4(dA, al0,al1,al2,al2, __float_as_uint(bh.x), __float_as_uint(bh.y));
                mma4(dA, ah0,ah1,ah2,ah2, __float_as_uint(bl.x), __float_as_uint(bl.y));
                mma4(dB, ah0,ah1,ah2,ah2, __float_as_uint(bh.z), __float_as_uint(bh.w));
                mma4(dB, al0,al1,al2,al2, __float_as_uint(bh.z), __float_as_uint(bh.w));
                mma4(dB, ah0,ah1,ah2,ah2, __float_as_uint(bl.z), __float_as_uint(bl.w));
                u32 r0 = h2u(__floats2half2_rn(fmaxf(dA[0],0.f), fmaxf(dA[1],0.f)));
                u32 r1 = h2u(__floats2half2_rn(fmaxf(dA[2],0.f), fmaxf(dA[3],0.f)));
                u32 r2 = h2u(__floats2half2_rn(fmaxf(dB[0],0.f), fmaxf(dB[1],0.f)));
                u32 r3 = h2u(__floats2half2_rn(fmaxf(dB[2],0.f), fmaxf(dB[3],0.f)));
                STM4(actA + (u32)(n2g*32), r0,r1,r2,r3);
            }
        }
        // sync the (w, w+8) pair that shares rows rA
        asm volatile("bar.sync %0, 64;" :: "r"(wl+1) : "memory");

        // ---- GEMM2: p_c = h @ w2 (ldmatrix A) ----
        float d2[4][4];
#pragma unroll
        for (int n=0;n<4;n++){ d2[n][0]=0.f; d2[n][1]=0.f; d2[n][2]=0.f; d2[n][3]=0.f; }
        {
            int n2b = lowhalf ? 0 : 2;
#pragma unroll
            for (int K=0;K<8;K++){
                u32 a0,a1,a2,a3;
                LDM4(a0,a1,a2,a3, actA + (u32)(K*32));
                float4 bA = *(float4*)&sm[F_W2F + ((K*4+n2b  )*32+lid)*4];
                float4 bB = *(float4*)&sm[F_W2F + ((K*4+n2b+1)*32+lid)*4];
                mma16(d2[0], a0,a1,a2,a3, __float_as_uint(bA.x), __float_as_uint(bA.y));
                mma16(d2[1], a0,a1,a2,a3, __float_as_uint(bA.z), __float_as_uint(bA.w));
                mma16(d2[2], a0,a1,a2,a3, __float_as_uint(bB.x), __float_as_uint(bB.y));
                mma16(d2[3], a0,a1,a2,a3, __float_as_uint(bB.z), __float_as_uint(bB.w));
            }
        }
        // write px = [p_c + b2 | x] via stmatrix / uint2
        {
            int nb = lowhalf ? 0 : 4;
#pragma unroll
            for (int pair=0; pair<2; pair++){
                int n0 = 2*pair, n1 = n0+1;
                int cA = (nb+n0)*8 + 2*tq, cB = (nb+n1)*8 + 2*tq;
                float bAa = sm[F_B2+cA], bAb = sm[F_B2+cA+1];
                float bBa = sm[F_B2+cB], bBb = sm[F_B2+cB+1];
                u32 r0 = h2u(__floats2half2_rn(d2[n0][0]+bAa, d2[n0][1]+bAb));
                u32 r1 = h2u(__floats2half2_rn(d2[n0][2]+bAa, d2[n0][3]+bAb));
                u32 r2 = h2u(__floats2half2_rn(d2[n1][0]+bBa, d2[n1][1]+bBb));
                u32 r3 = h2u(__floats2half2_rn(d2[n1][2]+bBa, d2[n1][3]+bBb));
                STM4(actA + (u32)(nb*16 + pair*32), r0,r1,r2,r3);
            }
#pragma unroll
            for (int i=0;i<4;i++)
                *(uint2*)(acth + xrow*136 + 64 + xcol + i*4) = *(uint2*)&xh[2*i];
        }
        __syncthreads();

        // ---- GEMM3: logits = px @ ws (ldmatrix A, mt=2, nt=4) ----
        float d3[2][4][4];
#pragma unroll
        for (int m=0;m<2;m++)
#pragma unroll
            for (int n=0;n<4;n++){ d3[m][n][0]=0.f; d3[m][n][1]=0.f; d3[m][n][2]=0.f; d3[m][n][3]=0.f; }
        {
#pragma unroll
            for (int K=0;K<8;K++){
                u32 a[2][4];
#pragma unroll
                for (int m=0;m<2;m++)
                    LDM4(a[m][0],a[m][1],a[m][2],a[m][3], base3[m] + (u32)(K*32));
                float4 bA = *(float4*)&sm[F_WSF + ((K*8 + 2*cg  )*32+lid)*4];
                float4 bB = *(float4*)&sm[F_WSF + ((K*8 + 2*cg+1)*32+lid)*4];
#pragma unroll
                for (int m=0;m<2;m++){
                    mma16(d3[m][0], a[m][0],a[m][1],a[m][2],a[m][3], __float_as_uint(bA.x), __float_as_uint(bA.y));
                    mma16(d3[m][1], a[m][0],a[m][1],a[m][2],a[m][3], __float_as_uint(bA.z), __float_as_uint(bA.w));
                    mma16(d3[m][2], a[m][0],a[m][1],a[m][2],a[m][3], __float_as_uint(bB.x), __float_as_uint(bB.y));
                    mma16(d3[m][3], a[m][0],a[m][1],a[m][2],a[m][3], __float_as_uint(bB.z), __float_as_uint(bB.w));
                }
            }
        }

        // ---- softmax over k + pooled feat (px via ldmatrix) ----
        {
            int fbase = half_*8;
#pragma unroll
            for (int m=0;m<2;m++){
                int pt = 2*rg + m;
#pragma unroll
                for (int pb2=0; pb2<2; pb2++){
                    u32 q0,q1,q2,q3;
                    LDM4(q0,q1,q2,q3, base3[m] + (u32)(cg*64 + pb2*32));
#pragma unroll
                    for (int sub=0; sub<2; sub++){
                        int nl = 2*pb2 + sub;
                        int c0 = (4*cg+nl)*8 + 2*tq;
                        u32 ulo = sub? q2 : q0;
                        u32 uhi = sub? q3 : q1;
                        float2 plo = __half22float2(*(__half2*)&ulo);
                        float2 phi = __half22float2(*(__half2*)&uhi);
                        float e0 = __expf(d3[m][nl][0]), e1 = __expf(d3[m][nl][1]);
                        float e2 = __expf(d3[m][nl][2]), e3 = __expf(d3[m][nl][3]);
                        float se = e0+e2, so_ = e1+e3;
                        float ve = fmaf(e0, plo.x, e2*phi.x);
                        float vo = fmaf(e1, plo.y, e3*phi.y);
#pragma unroll
                        for (int mm=4;mm<32;mm<<=1){
                            se += __shfl_xor_sync(0xffffffffu, se, mm);
                            so_ += __shfl_xor_sync(0xffffffffu, so_, mm);
                            ve += __shfl_xor_sync(0xffffffffu, ve, mm);
                            vo += __shfl_xor_sync(0xffffffffu, vo, mm);
                        }
                        if (lid < 4)
                            *(u32*)(feath + (fbase+pt)*136 + c0) =
                                h2u(__floats2half2_rn(ve/se, vo/so_));
                    }
                }
            }
        }

        if (half_ == 0){
            tprev = t; half_ = 1;
            __syncthreads();
        } else {
            __syncthreads();
            // ---- paired epilogue: 16 FEAT rows @ wo ----
            if (lowhalf){
                float d[4] = {0.f,0.f,0.f,0.f};
#pragma unroll
                for (int K=0;K<8;K++){
                    u32 a0,a1,a2,a3;
                    LDM4(a0,a1,a2,a3, fb + lmoff + (u32)(K*32));
                    uint2 bv = *(uint2*)&sm[F_WOF + ((K*8+w)*32+lid)*2];
                    mma16(d, a0,a1,a2,a3, bv.x, bv.y);
                }
                int c0 = w*8 + 2*tq;
                float ba = sm[F_BO+c0], bb = sm[F_BO+c0+1];
                float v0 = d[0]+ba, v1 = d[1]+bb;   // FEAT row g   -> tprev point g
                float v2 = d[2]+ba, v3 = d[3]+bb;   // FEAT row g+8 -> t     point g
                float2 va; va.x=v0; va.y=v1;
                float2 vb; vb.x=v2; vb.y=v3;
                *(float2*)&out[((size_t)tprev*8 + g)*64 + c0] = va;
                *(float2*)&out[((size_t)t*8     + g)*64 + c0] = vb;
                bs0 += v0+v2; bq0 += fmaf(v0,v0,v2*v2);
                bs1 += v1+v3; bq1 += fmaf(v1,v1,v3*v3);
            }
            half_ = 0;
        }
    }

    // ---- tail: one unpaired tile in FEAT rows 0-7 ----
    if (half_ && lowhalf){
        float d[4] = {0.f,0.f,0.f,0.f};
#pragma unroll
        for (int K=0;K<8;K++){
            u32 a0,a1,a2,a3;
            LDM4(a0,a1,a2,a3, fb + lmoff + (u32)(K*32));
            uint2 bv = *(uint2*)&sm[F_WOF + ((K*8+w)*32+lid)*2];
            mma16(d, a0,a1,a2,a3, bv.x, bv.y);
        }
        int c0 = w*8 + 2*tq;
        float ba = sm[F_BO+c0], bb = sm[F_BO+c0+1];
        float v0 = d[0]+ba, v1 = d[1]+bb;
        float2 va; va.x=v0; va.y=v1;
        *(float2*)&out[((size_t)tprev*8 + g)*64 + c0] = va;
        bs0 += v0; bq0 += v0*v0;
        bs1 += v1; bq1 += v1*v1;
    }

    if (lowhalf){
        int c0 = w*8 + 2*tq;
        atomicAdd(&sm[F_BNS+c0  ], bs0);
        atomicAdd(&sm[F_BNS+c0+1], bs1);
        atomicAdd(&sm[F_BNQ+c0  ], bq0);
        atomicAdd(&sm[F_BNQ+c0+1], bq1);
    }
    __syncthreads();
    if (tid < 64){
        atomicAdd(&g_sum2[tid],   sm[F_BNS+tid]);
        atomicAdd(&g_sumsq2[tid], sm[F_BNQ+tid]);
    }
}

__global__ void k_fin(const float* __restrict__ g2, const float* __restrict__ be2){
    int j = threadIdx.x;
    double inv = 1.0/(double)Nn;
    double mu  = (double)g_sum2[j]*inv;
    double var = (double)g_sumsq2[j]*inv - mu*mu;
    double a2  = (double)g2[j] / sqrt(var + 1e-5);
    g_a2[j] = (float)a2;
    g_c2[j] = (float)((double)be2[j] - mu*a2);
}

__global__ void k_norm(float* __restrict__ out){
    __shared__ float a2s[64], c2s[64];
    if (threadIdx.x < 64){ a2s[threadIdx.x]=g_a2[threadIdx.x]; c2s[threadIdx.x]=g_c2[threadIdx.x]; }
    __syncthreads();
    const int nq = Nn*64/4;
    float4* o4 = (float4*)out;
    for (int f = blockIdx.x*blockDim.x + threadIdx.x; f < nq; f += gridDim.x*blockDim.x){
        float4 v = o4[f];
        int j = (f*4) & 63;
        v.x = fmaxf(fmaf(v.x, a2s[j],   c2s[j]),   0.f);
        v.y = fmaxf(fmaf(v.y, a2s[j+1], c2s[j+1]), 0.f);
        v.z = fmaxf(fmaf(v.z, a2s[j+2], c2s[j+2]), 0.f);
        v.w = fmaxf(fmaf(v.w, a2s[j+3], c2s[j+3]), 0.f);
        o4[f] = v;
    }
}

extern "C" void kernel_launch(void* const* d_in, const int* in_sizes, int n_in,
                              void* d_out, int out_size){
    const float* p   = (const float*)d_in[0];
    const float* x   = (const float*)d_in[1];
    const float* w1  = (const float*)d_in[2];
    const float* g1  = (const float*)d_in[4];
    const float* be1 = (const float*)d_in[5];
    const float* w2  = (const float*)d_in[6];
    const float* b2  = (const float*)d_in[7];
    const float* ws  = (const float*)d_in[8];
    const float* wo  = (const float*)d_in[9];
    const float* bo  = (const float*)d_in[10];
    const float* g2  = (const float*)d_in[11];
    const float* be2 = (const float*)d_in[12];
    float* out = (float*)d_out;
    (void)in_sizes; (void)n_in; (void)out_size;

    cudaFuncSetAttribute(k_main, cudaFuncAttributeMaxDynamicSharedMemorySize, SMEM_BYTES);

    k_zero<<<1,64>>>();
    k_stats<<<256,256>>>(p);
    k_fold<<<1,128>>>(w1,g1,be1);
    k_main<<<GRID_MAIN,NT,SMEM_BYTES>>>(p,x,w2,b2,ws,wo,bo,out);
    k_fin<<<1,64>>>(g2,be2);
    k_norm<<<2048,256>>>(out);
}

// round 16
// speedup vs baseline: 2.4253x; 1.0243x over previous
#include <cuda_runtime.h>
#include <cuda_fp16.h>
typedef unsigned int u32;

#define Nn 65536
#define NK (Nn*16)
#define NTILES (Nn/8)
#define NT 512
#define GRID_MAIN 148

// ---- k_main float offsets in dynamic smem ----
#define F_ACT0  0          // halves: 128 x 136 = 8704 floats
#define F_ACT1  8704
#define F_W1FH  17408      // 1024
#define F_W1FL  18432      // 1024
#define F_W2F   19456      // 4096
#define F_WSF   23552      // 8192
#define F_WOF   31744      // 4096
#define F_FEAT  35840      // two buffers of 16x136 halves = 2176 floats
#define F_B2    38016
#define F_BO    38080
#define F_BNS   38144
#define F_BNQ   38208
#define F_TOTAL 38272
#define SMEM_BYTES (F_TOTAL*4)

__device__ __forceinline__ float to_tf32(float x){
    float r; asm("cvt.rna.tf32.f32 %0, %1;":"=f"(r):"f"(x)); return r;
}
__device__ __forceinline__ void mma4(float* d, u32 a0, u32 a1, u32 a2, u32 a3,
                                     u32 b0, u32 b1){
    asm volatile("mma.sync.aligned.m16n8k8.row.col.f32.tf32.tf32.f32 "
        "{%0,%1,%2,%3}, {%4,%5,%6,%7}, {%8,%9}, {%0,%1,%2,%3};"
        : "+f"(d[0]),"+f"(d[1]),"+f"(d[2]),"+f"(d[3])
        : "r"(a0),"r"(a1),"r"(a2),"r"(a3),"r"(b0),"r"(b1));
}
__device__ __forceinline__ void mma16(float* d, u32 a0, u32 a1, u32 a2, u32 a3,
                                      u32 b0, u32 b1){
    asm volatile("mma.sync.aligned.m16n8k16.row.col.f32.f16.f16.f32 "
        "{%0,%1,%2,%3}, {%4,%5,%6,%7}, {%8,%9}, {%0,%1,%2,%3};"
        : "+f"(d[0]),"+f"(d[1]),"+f"(d[2]),"+f"(d[3])
        : "r"(a0),"r"(a1),"r"(a2),"r"(a3),"r"(b0),"r"(b1));
}
__device__ __forceinline__ u32 h2u(__half2 h){ return *(u32*)&h; }
__device__ __forceinline__ u32 cvta_sh(const void* p){
    u32 a; asm("{ .reg .u64 t; cvta.to.shared.u64 t, %1; cvt.u32.u64 %0, t; }":"=r"(a):"l"(p)); return a;
}
#define LDM4(r0,r1,r2,r3,addr) \
    asm volatile("ldmatrix.sync.aligned.m8n8.x4.shared.b16 {%0,%1,%2,%3}, [%4];" \
        : "=r"(r0),"=r"(r1),"=r"(r2),"=r"(r3) : "r"(addr))
#define STM4(addr,r0,r1,r2,r3) \
    asm volatile("stmatrix.sync.aligned.m8n8.x4.shared.b16 [%0], {%1,%2,%3,%4};" \
        :: "r"(addr),"r"(r0),"r"(r1),"r"(r2),"r"(r3))
#define BAR64(id) asm volatile("bar.sync %0, 64;" :: "r"(id) : "memory")

// ---- scratch globals ----
__device__ float g_M1[10], g_M2[55], g_w1p[1280], g_c1[128];
__device__ float g_sum2[64], g_sumsq2[64], g_a2[64], g_c2[64];

__global__ void k_zero(){
    int t = threadIdx.x;
    if (t < 10) g_M1[t]=0.f;
    if (t < 55) g_M2[t]=0.f;
    if (t < 64){ g_sum2[t]=0.f; g_sumsq2[t]=0.f; }
}

// ---- K1: concat moments, center-factored ----
__global__ void k_stats(const float* __restrict__ p){
    __shared__ float red[8][65];
    float m1[10], m2[55];
#pragma unroll
    for (int i=0;i<10;i++) m1[i]=0.f;
#pragma unroll
    for (int i=0;i<55;i++) m2[i]=0.f;

    int n = blockIdx.x*blockDim.x + threadIdx.x;
    {
        float4 pr[12];
        const float4* pp = (const float4*)(p + (size_t)n*48);
#pragma unroll
        for (int i=0;i<12;i++) pr[i] = pp[i];
        const float* pc = (const float*)pr;
        float C0=pc[0], C1=pc[1], C2=pc[2];
        float Sq0=0.f,Sq1=0.f,Sq2=0.f;
        float Q00=0.f,Q01=0.f,Q02=0.f,Q11=0.f,Q12=0.f,Q22=0.f;
        float Sd=0.f, Sdq0=0.f,Sdq1=0.f,Sdq2=0.f, Sdd=0.f;
#pragma unroll
        for (int k=0;k<16;k++){
            float qx=pc[3*k], qy=pc[3*k+1], qz=pc[3*k+2];
            float dx=C0-qx, dy=C1-qy, dz=C2-qz;
            float d2 = dx*dx + dy*dy + dz*dz;
            float ds = sqrtf(d2);
            Sq0+=qx; Sq1+=qy; Sq2+=qz;
            Q00=fmaf(qx,qx,Q00); Q01=fmaf(qx,qy,Q01); Q02=fmaf(qx,qz,Q02);
            Q11=fmaf(qy,qy,Q11); Q12=fmaf(qy,qz,Q12); Q22=fmaf(qz,qz,Q22);
            Sd+=ds; Sdq0=fmaf(ds,qx,Sdq0); Sdq1=fmaf(ds,qy,Sdq1); Sdq2=fmaf(ds,qz,Sdq2);
            Sdd+=d2;
        }
        float C[3]={C0,C1,C2};
        float Sq[3]={Sq0,Sq1,Sq2};
        float QQ[3][3]={{Q00,Q01,Q02},{Q01,Q11,Q12},{Q02,Q12,Q22}};
        float SDQ[3]={Sdq0,Sdq1,Sdq2};
#pragma unroll
        for (int i=0;i<3;i++){
            m1[i]   += 16.f*C[i];
            m1[3+i] += Sq[i];
            m1[6+i] += 16.f*C[i]-Sq[i];
        }
        m1[9] += Sd;
        int t = 0;
#pragma unroll
        for (int a=0;a<3;a++){
#pragma unroll
            for (int b=a;b<3;b++) m2[t++] += 16.f*C[a]*C[b];
#pragma unroll
            for (int b=0;b<3;b++) m2[t++] += C[a]*Sq[b];
#pragma unroll
            for (int b=0;b<3;b++) m2[t++] += C[a]*(16.f*C[b]-Sq[b]);
            m2[t++] += C[a]*Sd;
        }
#pragma unroll
        for (int a=0;a<3;a++){
#pragma unroll
            for (int b=a;b<3;b++) m2[t++] += QQ[a][b];
#pragma unroll
            for (int b=0;b<3;b++) m2[t++] += C[b]*Sq[a]-QQ[a][b];
            m2[t++] += SDQ[a];
        }
#pragma unroll
        for (int a=0;a<3;a++){
#pragma unroll
            for (int b=a;b<3;b++)
                m2[t++] += 16.f*C[a]*C[b]-C[a]*Sq[b]-C[b]*Sq[a]+QQ[a][b];
            m2[t++] += C[a]*Sd - SDQ[a];
        }
        m2[t++] += Sdd;
    }
#pragma unroll
    for (int off=16; off>0; off>>=1){
#pragma unroll
        for (int i=0;i<10;i++) m1[i] += __shfl_down_sync(0xffffffffu, m1[i], off);
#pragma unroll
        for (int i=0;i<55;i++) m2[i] += __shfl_down_sync(0xffffffffu, m2[i], off);
    }
    int wid = threadIdx.x>>5;
    if ((threadIdx.x&31)==0){
#pragma unroll
        for (int i=0;i<10;i++) red[wid][i]=m1[i];
#pragma unroll
        for (int i=0;i<55;i++) red[wid][10+i]=m2[i];
    }
    __syncthreads();
    if (threadIdx.x < 65){
        float a=0.f;
#pragma unroll
        for (int w=0;w<8;w++) a += red[w][threadIdx.x];
        if (threadIdx.x < 10) atomicAdd(&g_M1[threadIdx.x], a);
        else atomicAdd(&g_M2[threadIdx.x-10], a);
    }
}

__global__ void k_fold(const float* __restrict__ w1, const float* __restrict__ g1,
                       const float* __restrict__ be1){
    int d = threadIdx.x;
    const double invNK = 1.0/(double)NK;
    double wv[10];
#pragma unroll
    for (int c=0;c<10;c++) wv[c] = (double)w1[c*128+d];
    double m = 0.0;
#pragma unroll
    for (int c=0;c<10;c++) m += ((double)g_M1[c]*invNK)*wv[c];
    double q = 0.0; int t = 0;
#pragma unroll
    for (int a=0;a<10;a++)
#pragma unroll
        for (int b=a;b<10;b++){
            double s2 = (double)g_M2[t++]*invNK;
            double term = s2*wv[a]*wv[b];
            q += (a==b) ? term : 2.0*term;
        }
    double var = q - m*m;
    double a1 = (double)g1[d] / sqrt(var + 1e-5);
    g_c1[d] = (float)((double)be1[d] - m*a1);
#pragma unroll
    for (int c=0;c<10;c++) g_w1p[c*128+d] = (float)(wv[c]*a1);
}

__device__ __forceinline__ float w8row(int r, int c){
    switch(r){
        case 0: return g_w1p[384+c] - g_w1p[768+c];
        case 1: return g_w1p[512+c] - g_w1p[896+c];
        case 2: return g_w1p[640+c] - g_w1p[1024+c];
        case 3: return g_w1p[1152+c];
        case 4: return g_w1p[c]     + g_w1p[768+c];
        case 5: return g_w1p[128+c] + g_w1p[896+c];
        case 6: return g_w1p[256+c] + g_w1p[1024+c];
        default: return g_c1[c];
    }
}

__global__ void __launch_bounds__(NT,1) k_main(
    const float* __restrict__ p, const float* __restrict__ x,
    const float* __restrict__ w2, const float* __restrict__ b2,
    const float* __restrict__ ws, const float* __restrict__ wo,
    const float* __restrict__ bo, float* __restrict__ out)
{
    extern __shared__ float sm[];
    int tid = threadIdx.x, w = tid>>5, lid = tid&31;
    int g = lid>>2, tq = lid&3;
    int wl = w & 7;
    int rA = wl*16;
    bool lowhalf = (w < 8);
    int rg = w & 3, cg = w >> 2;
    int row0 = rg*32;

    // ---- stage fp16 weight fragments ----
    for (int i = tid; i < 1024; i += NT){          // w2
        int lane = i&31, j = (i>>5)&3, K = i>>7;
        int g2 = lane>>2, t2 = lane&3;
        int r0 = K*16 + 2*t2;
        int c0 = (2*j)*8 + g2, c1 = (2*j+1)*8 + g2;
        uint4 v;
        v.x = h2u(__floats2half2_rn(w2[r0*64+c0],     w2[(r0+1)*64+c0]));
        v.y = h2u(__floats2half2_rn(w2[(r0+8)*64+c0], w2[(r0+9)*64+c0]));
        v.z = h2u(__floats2half2_rn(w2[r0*64+c1],     w2[(r0+1)*64+c1]));
        v.w = h2u(__floats2half2_rn(w2[(r0+8)*64+c1], w2[(r0+9)*64+c1]));
        *(uint4*)&sm[F_W2F + i*4] = v;
    }
    for (int i = tid; i < 2048; i += NT){          // ws
        int lane = i&31, j = (i>>5)&7, K = i>>8;
        int g2 = lane>>2, t2 = lane&3;
        int r0 = K*16 + 2*t2;
        int c0 = (2*j)*8 + g2, c1 = (2*j+1)*8 + g2;
        uint4 v;
        v.x = h2u(__floats2half2_rn(ws[r0*128+c0],     ws[(r0+1)*128+c0]));
        v.y = h2u(__floats2half2_rn(ws[(r0+8)*128+c0], ws[(r0+9)*128+c0]));
        v.z = h2u(__floats2half2_rn(ws[r0*128+c1],     ws[(r0+1)*128+c1]));
        v.w = h2u(__floats2half2_rn(ws[(r0+8)*128+c1], ws[(r0+9)*128+c1]));
        *(uint4*)&sm[F_WSF + i*4] = v;
    }
    for (int i = tid; i < 2048; i += NT){          // wo
        int lane = i&31, n = (i>>5)&7, K = i>>8;
        int g2 = lane>>2, t2 = lane&3;
        int r0 = K*16 + 2*t2, c = n*8 + g2;
        uint2 v;
        v.x = h2u(__floats2half2_rn(wo[r0*64+c],     wo[(r0+1)*64+c]));
        v.y = h2u(__floats2half2_rn(wo[(r0+8)*64+c], wo[(r0+9)*64+c]));
        *(uint2*)&sm[F_WOF + i*2] = v;
    }
    if (tid < 256){                                // layer1 B frags (tf32 hi/lo)
        int i = tid, l2 = i&31, n2 = (i>>5)&7;
        int g2 = l2>>2, t2 = l2&3;
#pragma unroll
        for (int j=0;j<2;j++){
            int c = (2*n2+j)*8 + g2;
            float v0 = w8row(t2,   c);
            float v1 = w8row(t2+4, c);
            float h0 = to_tf32(v0), h1 = to_tf32(v1);
            sm[F_W1FH + (n2*32+l2)*4 + 2*j  ] = h0;
            sm[F_W1FH + (n2*32+l2)*4 + 2*j+1] = h1;
            sm[F_W1FL + (n2*32+l2)*4 + 2*j  ] = to_tf32(v0-h0);
            sm[F_W1FL + (n2*32+l2)*4 + 2*j+1] = to_tf32(v1-h1);
        }
    }
    if (tid < 64){ sm[F_B2+tid]=b2[tid]; sm[F_BO+tid]=bo[tid]; sm[F_BNS+tid]=0.f; sm[F_BNQ+tid]=0.f; }
    __syncthreads();

    u32 smb = cvta_sh(sm);
    u32 lmoff = (u32)((lid&15)*272 + ((lid&16)?16:0));
    u32 actW[2], b3[2][2];
    actW[0] = smb + (u32)(F_ACT0*4 + rA*272) + lmoff;
    actW[1] = smb + (u32)(F_ACT1*4 + rA*272) + lmoff;
    b3[0][0] = smb + (u32)(F_ACT0*4 + row0*272) + lmoff;
    b3[0][1] = b3[0][0] + 16*272;
    b3[1][0] = smb + (u32)(F_ACT1*4 + row0*272) + lmoff;
    b3[1][1] = b3[1][0] + 16*272;
    __half* acthb[2] = { (__half*)(sm + F_ACT0), (__half*)(sm + F_ACT1) };

    float bs0=0.f, bs1=0.f, bq0=0.f, bq1=0.f;
    int xrow = wl*16 + (lid>>1);
    int xcol = (lowhalf?0:32) + (lid&1)*16;
    int fbuf = 0;

    for (int t0 = blockIdx.x*2; t0 < NTILES; t0 += gridDim.x*2){
        int tiles[2] = { t0, t0+1 };

        // prefetch x for both tiles -> fp16 pairs
        u32 xh[2][8];
#pragma unroll
        for (int tb=0; tb<2; tb++){
            const float4* xp = (const float4*)(x + ((size_t)tiles[tb]*128 + xrow)*64 + xcol);
#pragma unroll
            for (int i=0;i<4;i++){
                float4 v = xp[i];
                xh[tb][2*i]   = h2u(__floats2half2_rn(v.x, v.y));
                xh[tb][2*i+1] = h2u(__floats2half2_rn(v.z, v.w));
            }
        }

        // ---- GEMM1 both tiles ----
#pragma unroll
        for (int tb=0; tb<2; tb++){
            u32 ah0, ah1, ah2, al0, al1, al2;
            {
                const float* pb = p + (size_t)tiles[tb]*384 + wl*48;
                float cxv=pb[0], cyv=pb[1], czv=pb[2];
                float qa0=pb[3*g],    qa1=pb[3*g+1],  qa2=pb[3*g+2];
                float qb0=pb[3*g+24], qb1=pb[3*g+25], qb2=pb[3*g+26];
                float da0=cxv-qa0, da1=cyv-qa1, da2=czv-qa2;
                float db0=cxv-qb0, db1=cyv-qb1, db2=czv-qb2;
                float dsa=sqrtf(da0*da0+da1*da1+da2*da2);
                float dsb=sqrtf(db0*db0+db1*db1+db2*db2);
                float va = (tq==0)?qa0:(tq==1)?qa1:(tq==2)?qa2:dsa;
                float vb = (tq==0)?qb0:(tq==1)?qb1:(tq==2)?qb2:dsb;
                float wa = (tq==0)?cxv:(tq==1)?cyv:(tq==2)?czv:1.f;
                float h0=to_tf32(va), h1=to_tf32(vb), h2=to_tf32(wa);
                ah0=__float_as_uint(h0); al0=__float_as_uint(to_tf32(va-h0));
                ah1=__float_as_uint(h1); al1=__float_as_uint(to_tf32(vb-h1));
                ah2=__float_as_uint(h2); al2=__float_as_uint(to_tf32(wa-h2));
            }
            int n2b = lowhalf ? 0 : 4;
#pragma unroll
            for (int j=0;j<4;j++){
                int n2g = n2b + j;
                float4 bh = *(float4*)&sm[F_W1FH + (n2g*32+lid)*4];
                float4 bl = *(float4*)&sm[F_W1FL + (n2g*32+lid)*4];
                float dA[4] = {0.f,0.f,0.f,0.f};
                float dB[4] = {0.f,0.f,0.f,0.f};
                mma4(dA, ah0,ah1,ah2,ah2, __float_as_uint(bh.x), __float_as_uint(bh.y));
                mma4(dA, al0,al1,al2,al2, __float_as_uint(bh.x), __float_as_uint(bh.y));
                mma4(dA, ah0,ah1,ah2,ah2, __float_as_uint(bl.x), __float_as_uint(bl.y));
                mma4(dB, ah0,ah1,ah2,ah2, __float_as_uint(bh.z), __float_as_uint(bh.w));
                mma4(dB, al0,al1,al2,al2, __float_as_uint(bh.z), __float_as_uint(bh.w));
                mma4(dB, ah0,ah1,ah2,ah2, __float_as_uint(bl.z), __float_as_uint(bl.w));
                u32 r0 = h2u(__floats2half2_rn(fmaxf(dA[0],0.f), fmaxf(dA[1],0.f)));
                u32 r1 = h2u(__floats2half2_rn(fmaxf(dA[2],0.f), fmaxf(dA[3],0.f)));
                u32 r2 = h2u(__floats2half2_rn(fmaxf(dB[0],0.f), fmaxf(dB[1],0.f)));
                u32 r3 = h2u(__floats2half2_rn(fmaxf(dB[2],0.f), fmaxf(dB[3],0.f)));
                STM4(actW[tb] + (u32)(n2g*32), r0,r1,r2,r3);
            }
        }
        BAR64(wl+1);

        // ---- GEMM2 + px writes both tiles (pair-barrier between read & write) ----
#pragma unroll
        for (int tb=0; tb<2; tb++){
            float d2[4][4];
#pragma unroll
            for (int n=0;n<4;n++){ d2[n][0]=0.f; d2[n][1]=0.f; d2[n][2]=0.f; d2[n][3]=0.f; }
            int n2b = lowhalf ? 0 : 2;
#pragma unroll
            for (int K=0;K<8;K++){
                u32 a0,a1,a2,a3;
                LDM4(a0,a1,a2,a3, actW[tb] + (u32)(K*32));
                float4 bA = *(float4*)&sm[F_W2F + ((K*4+n2b  )*32+lid)*4];
                float4 bB = *(float4*)&sm[F_W2F + ((K*4+n2b+1)*32+lid)*4];
                mma16(d2[0], a0,a1,a2,a3, __float_as_uint(bA.x), __float_as_uint(bA.y));
                mma16(d2[1], a0,a1,a2,a3, __float_as_uint(bA.z), __float_as_uint(bA.w));
                mma16(d2[2], a0,a1,a2,a3, __float_as_uint(bB.x), __float_as_uint(bB.y));
                mma16(d2[3], a0,a1,a2,a3, __float_as_uint(bB.z), __float_as_uint(bB.w));
            }
            // partner warp may still be reading h from this buffer — sync the pair
            BAR64(wl+1);
            int nb = lowhalf ? 0 : 4;
#pragma unroll
            for (int pair=0; pair<2; pair++){
                int n0 = 2*pair, n1 = n0+1;
                int cA = (nb+n0)*8 + 2*tq, cB = (nb+n1)*8 + 2*tq;
                float bAa = sm[F_B2+cA], bAb = sm[F_B2+cA+1];
                float bBa = sm[F_B2+cB], bBb = sm[F_B2+cB+1];
                u32 r0 = h2u(__floats2half2_rn(d2[n0][0]+bAa, d2[n0][1]+bAb));
                u32 r1 = h2u(__floats2half2_rn(d2[n0][2]+bAa, d2[n0][3]+bAb));
                u32 r2 = h2u(__floats2half2_rn(d2[n1][0]+bBa, d2[n1][1]+bBb));
                u32 r3 = h2u(__floats2half2_rn(d2[n1][2]+bBa, d2[n1][3]+bBb));
                STM4(actW[tb] + (u32)(nb*16 + pair*32), r0,r1,r2,r3);
            }
#pragma unroll
            for (int i=0;i<4;i++)
                *(uint2*)(acthb[tb] + xrow*136 + 64 + xcol + i*4) = *(uint2*)&xh[tb][2*i];
        }
        __syncthreads();

        // ---- GEMM3 + softmax both tiles ----
        __half* feath = (__half*)(sm + F_FEAT) + fbuf*2176;
#pragma unroll
        for (int tb=0; tb<2; tb++){
            float d3[2][4][4];
#pragma unroll
            for (int m=0;m<2;m++)
#pragma unroll
                for (int n=0;n<4;n++){ d3[m][n][0]=0.f; d3[m][n][1]=0.f; d3[m][n][2]=0.f; d3[m][n][3]=0.f; }
#pragma unroll
            for (int K=0;K<8;K++){
                u32 a[2][4];
#pragma unroll
                for (int m=0;m<2;m++)
                    LDM4(a[m][0],a[m][1],a[m][2],a[m][3], b3[tb][m] + (u32)(K*32));
                float4 bA = *(float4*)&sm[F_WSF + ((K*8 + 2*cg  )*32+lid)*4];
                float4 bB = *(float4*)&sm[F_WSF + ((K*8 + 2*cg+1)*32+lid)*4];
#pragma unroll
                for (int m=0;m<2;m++){
                    mma16(d3[m][0], a[m][0],a[m][1],a[m][2],a[m][3], __float_as_uint(bA.x), __float_as_uint(bA.y));
                    mma16(d3[m][1], a[m][0],a[m][1],a[m][2],a[m][3], __float_as_uint(bA.z), __float_as_uint(bA.w));
                    mma16(d3[m][2], a[m][0],a[m][1],a[m][2],a[m][3], __float_as_uint(bB.x), __float_as_uint(bB.y));
                    mma16(d3[m][3], a[m][0],a[m][1],a[m][2],a[m][3], __float_as_uint(bB.z), __float_as_uint(bB.w));
                }
            }
            int fbase = tb*8;
#pragma unroll
            for (int m=0;m<2;m++){
                int pt = 2*rg + m;
#pragma unroll
                for (int pb2=0; pb2<2; pb2++){
                    u32 q0,q1,q2,q3;
                    LDM4(q0,q1,q2,q3, b3[tb][m] + (u32)(cg*64 + pb2*32));
#pragma unroll
                    for (int sub=0; sub<2; sub++){
                        int nl = 2*pb2 + sub;
                        int c0 = (4*cg+nl)*8 + 2*tq;
                        u32 ulo = sub? q2 : q0;
                        u32 uhi = sub? q3 : q1;
                        float2 plo = __half22float2(*(__half2*)&ulo);
                        float2 phi = __half22float2(*(__half2*)&uhi);
                        float e0 = __expf(d3[m][nl][0]), e1 = __expf(d3[m][nl][1]);
                        float e2 = __expf(d3[m][nl][2]), e3 = __expf(d3[m][nl][3]);
                        float se = e0+e2, so_ = e1+e3;
                        float ve = fmaf(e0, plo.x, e2*phi.x);
                        float vo = fmaf(e1, plo.y, e3*phi.y);
#pragma unroll
                        for (int mm=4;mm<32;mm<<=1){
                            se += __shfl_xor_sync(0xffffffffu, se, mm);
                            so_ += __shfl_xor_sync(0xffffffffu, so_, mm);
                            ve += __shfl_xor_sync(0xffffffffu, ve, mm);
                            vo += __shfl_xor_sync(0xffffffffu, vo, mm);
                        }
                        if (lid < 4)
                            *(u32*)(feath + (fbase+pt)*136 + c0) =
                                h2u(__floats2half2_rn(ve/se, vo/so_));
                    }
                }
            }
        }
        __syncthreads();

        // ---- epilogue: 16 FEAT rows @ wo (tile A rows 0-7, tile B rows 8-15) ----
        if (lowhalf){
            u32 fb = smb + (u32)(F_FEAT*4 + fbuf*4352) + lmoff;
            float d[4] = {0.f,0.f,0.f,0.f};
#pragma unroll
            for (int K=0;K<8;K++){
                u32 a0,a1,a2,a3;
                LDM4(a0,a1,a2,a3, fb + (u32)(K*32));
                uint2 bv = *(uint2*)&sm[F_WOF + ((K*8+w)*32+lid)*2];
                mma16(d, a0,a1,a2,a3, bv.x, bv.y);
            }
            int c0 = w*8 + 2*tq;
            float ba = sm[F_BO+c0], bb = sm[F_BO+c0+1];
            float v0 = d[0]+ba, v1 = d[1]+bb;   // FEAT row g   -> tile A point g
            float v2 = d[2]+ba, v3 = d[3]+bb;   // FEAT row g+8 -> tile B point g
            float2 va; va.x=v0; va.y=v1;
            float2 vb; vb.x=v2; vb.y=v3;
            *(float2*)&out[((size_t)tiles[0]*8 + g)*64 + c0] = va;
            *(float2*)&out[((size_t)tiles[1]*8 + g)*64 + c0] = vb;
            bs0 += v0+v2; bq0 += fmaf(v0,v0,v2*v2);
            bs1 += v1+v3; bq1 += fmaf(v1,v1,v3*v3);
        }
        fbuf ^= 1;
    }

    if (lowhalf){
        int c0 = w*8 + 2*tq;
        atomicAdd(&sm[F_BNS+c0  ], bs0);
        atomicAdd(&sm[F_BNS+c0+1], bs1);
        atomicAdd(&sm[F_BNQ+c0  ], bq0);
        atomicAdd(&sm[F_BNQ+c0+1], bq1);
    }
    __syncthreads();
    if (tid < 64){
        atomicAdd(&g_sum2[tid],   sm[F_BNS+tid]);
        atomicAdd(&g_sumsq2[tid], sm[F_BNQ+tid]);
    }
}

__global__ void k_fin(const float* __restrict__ g2, const float* __restrict__ be2){
    int j = threadIdx.x;
    double inv = 1.0/(double)Nn;
    double mu  = (double)g_sum2[j]*inv;
    double var = (double)g_sumsq2[j]*inv - mu*mu;
    double a2  = (double)g2[j] / sqrt(var + 1e-5);
    g_a2[j] = (float)a2;
    g_c2[j] = (float)((double)be2[j] - mu*a2);
}

__global__ void k_norm(float* __restrict__ out){
    __shared__ float a2s[64], c2s[64];
    if (threadIdx.x < 64){ a2s[threadIdx.x]=g_a2[threadIdx.x]; c2s[threadIdx.x]=g_c2[threadIdx.x]; }
    __syncthreads();
    const int nq = Nn*64/4;
    float4* o4 = (float4*)out;
    for (int f = blockIdx.x*blockDim.x + threadIdx.x; f < nq; f += gridDim.x*blockDim.x){
        float4 v = o4[f];
        int j = (f*4) & 63;
        v.x = fmaxf(fmaf(v.x, a2s[j],   c2s[j]),   0.f);
        v.y = fmaxf(fmaf(v.y, a2s[j+1], c2s[j+1]), 0.f);
        v.z = fmaxf(fmaf(v.z, a2s[j+2], c2s[j+2]), 0.f);
        v.w = fmaxf(fmaf(v.w, a2s[j+3], c2s[j+3]), 0.f);
        o4[f] = v;
    }
}

extern "C" void kernel_launch(void* const* d_in, const int* in_sizes, int n_in,
                              void* d_out, int out_size){
    const float* p   = (const float*)d_in[0];
    const float* x   = (const float*)d_in[1];
    const float* w1  = (const float*)d_in[2];
    const float* g1  = (const float*)d_in[4];
    const float* be1 = (const float*)d_in[5];
    const float* w2  = (const float*)d_in[6];
    const float* b2  = (const float*)d_in[7];
    const float* ws  = (const float*)d_in[8];
    const float* wo  = (const float*)d_in[9];
    const float* bo  = (const float*)d_in[10];
    const float* g2  = (const float*)d_in[11];
    const float* be2 = (const float*)d_in[12];
    float* out = (float*)d_out;
    (void)in_sizes; (void)n_in; (void)out_size;

    cudaFuncSetAttribute(k_main, cudaFuncAttributeMaxDynamicSharedMemorySize, SMEM_BYTES);

    k_zero<<<1,64>>>();
    k_stats<<<256,256>>>(p);
    k_fold<<<1,128>>>(w1,g1,be1);
    k_main<<<GRID_MAIN,NT,SMEM_BYTES>>>(p,x,w2,b2,ws,wo,bo,out);
    k_fin<<<1,64>>>(g2,be2);
    k_norm<<<2048,256>>>(out);
}

// round 17
// speedup vs baseline: 2.6427x; 1.0896x over previous
#include <cuda_runtime.h>
#include <cuda_fp16.h>
typedef unsigned int u32;

#define Nn 65536
#define NK (Nn*16)
#define NTILES (Nn/8)
#define NT 512
#define GRID_MAIN 148

// ---- k_main float offsets in dynamic smem ----
#define F_ACT0  0          // halves: 128 x 136 = 8704 floats
#define F_ACT1  8704
#define F_W1F16 17408      // 256 x uint2 = 512 floats
#define F_W2F   17920      // 4096
#define F_WSF   22016      // 8192
#define F_WOF   30208      // 4096
#define F_FEAT  34304      // two buffers of 16x136 halves = 2176 floats
#define F_B2    36480
#define F_BO    36544
#define F_BNS   36608
#define F_BNQ   36672
#define F_TOTAL 36736
#define SMEM_BYTES (F_TOTAL*4)

__device__ __forceinline__ void mma16(float* d, u32 a0, u32 a1, u32 a2, u32 a3,
                                      u32 b0, u32 b1){
    asm volatile("mma.sync.aligned.m16n8k16.row.col.f32.f16.f16.f32 "
        "{%0,%1,%2,%3}, {%4,%5,%6,%7}, {%8,%9}, {%0,%1,%2,%3};"
        : "+f"(d[0]),"+f"(d[1]),"+f"(d[2]),"+f"(d[3])
        : "r"(a0),"r"(a1),"r"(a2),"r"(a3),"r"(b0),"r"(b1));
}
__device__ __forceinline__ u32 h2u(__half2 h){ return *(u32*)&h; }
__device__ __forceinline__ u32 cvta_sh(const void* p){
    u32 a; asm("{ .reg .u64 t; cvta.to.shared.u64 t, %1; cvt.u32.u64 %0, t; }":"=r"(a):"l"(p)); return a;
}
#define LDM4(r0,r1,r2,r3,addr) \
    asm volatile("ldmatrix.sync.aligned.m8n8.x4.shared.b16 {%0,%1,%2,%3}, [%4];" \
        : "=r"(r0),"=r"(r1),"=r"(r2),"=r"(r3) : "r"(addr))
#define STM4(addr,r0,r1,r2,r3) \
    asm volatile("stmatrix.sync.aligned.m8n8.x4.shared.b16 [%0], {%1,%2,%3,%4};" \
        :: "r"(addr),"r"(r0),"r"(r1),"r"(r2),"r"(r3))
#define BAR64(id) asm volatile("bar.sync %0, 64;" :: "r"(id) : "memory")

// ---- scratch globals ----
__device__ float g_M1[10], g_M2[55], g_w1p[1280], g_c1[128];
__device__ float g_sum2[64], g_sumsq2[64], g_a2[64], g_c2[64];

__global__ void k_zero(){
    int t = threadIdx.x;
    if (t < 10) g_M1[t]=0.f;
    if (t < 55) g_M2[t]=0.f;
    if (t < 64){ g_sum2[t]=0.f; g_sumsq2[t]=0.f; }
}

// ---- K1: concat moments, center-factored ----
__global__ void k_stats(const float* __restrict__ p){
    __shared__ float red[8][65];
    float m1[10], m2[55];
#pragma unroll
    for (int i=0;i<10;i++) m1[i]=0.f;
#pragma unroll
    for (int i=0;i<55;i++) m2[i]=0.f;

    int n = blockIdx.x*blockDim.x + threadIdx.x;
    {
        float4 pr[12];
        const float4* pp = (const float4*)(p + (size_t)n*48);
#pragma unroll
        for (int i=0;i<12;i++) pr[i] = pp[i];
        const float* pc = (const float*)pr;
        float C0=pc[0], C1=pc[1], C2=pc[2];
        float Sq0=0.f,Sq1=0.f,Sq2=0.f;
        float Q00=0.f,Q01=0.f,Q02=0.f,Q11=0.f,Q12=0.f,Q22=0.f;
        float Sd=0.f, Sdq0=0.f,Sdq1=0.f,Sdq2=0.f, Sdd=0.f;
#pragma unroll
        for (int k=0;k<16;k++){
            float qx=pc[3*k], qy=pc[3*k+1], qz=pc[3*k+2];
            float dx=C0-qx, dy=C1-qy, dz=C2-qz;
            float d2 = dx*dx + dy*dy + dz*dz;
            float ds = sqrtf(d2);
            Sq0+=qx; Sq1+=qy; Sq2+=qz;
            Q00=fmaf(qx,qx,Q00); Q01=fmaf(qx,qy,Q01); Q02=fmaf(qx,qz,Q02);
            Q11=fmaf(qy,qy,Q11); Q12=fmaf(qy,qz,Q12); Q22=fmaf(qz,qz,Q22);
            Sd+=ds; Sdq0=fmaf(ds,qx,Sdq0); Sdq1=fmaf(ds,qy,Sdq1); Sdq2=fmaf(ds,qz,Sdq2);
            Sdd+=d2;
        }
        float C[3]={C0,C1,C2};
        float Sq[3]={Sq0,Sq1,Sq2};
        float QQ[3][3]={{Q00,Q01,Q02},{Q01,Q11,Q12},{Q02,Q12,Q22}};
        float SDQ[3]={Sdq0,Sdq1,Sdq2};
#pragma unroll
        for (int i=0;i<3;i++){
            m1[i]   += 16.f*C[i];
            m1[3+i] += Sq[i];
            m1[6+i] += 16.f*C[i]-Sq[i];
        }
        m1[9] += Sd;
        int t = 0;
#pragma unroll
        for (int a=0;a<3;a++){
#pragma unroll
            for (int b=a;b<3;b++) m2[t++] += 16.f*C[a]*C[b];
#pragma unroll
            for (int b=0;b<3;b++) m2[t++] += C[a]*Sq[b];
#pragma unroll
            for (int b=0;b<3;b++) m2[t++] += C[a]*(16.f*C[b]-Sq[b]);
            m2[t++] += C[a]*Sd;
        }
#pragma unroll
        for (int a=0;a<3;a++){
#pragma unroll
            for (int b=a;b<3;b++) m2[t++] += QQ[a][b];
#pragma unroll
            for (int b=0;b<3;b++) m2[t++] += C[b]*Sq[a]-QQ[a][b];
            m2[t++] += SDQ[a];
        }
#pragma unroll
        for (int a=0;a<3;a++){
#pragma unroll
            for (int b=a;b<3;b++)
                m2[t++] += 16.f*C[a]*C[b]-C[a]*Sq[b]-C[b]*Sq[a]+QQ[a][b];
            m2[t++] += C[a]*Sd - SDQ[a];
        }
        m2[t++] += Sdd;
    }
#pragma unroll
    for (int off=16; off>0; off>>=1){
#pragma unroll
        for (int i=0;i<10;i++) m1[i] += __shfl_down_sync(0xffffffffu, m1[i], off);
#pragma unroll
        for (int i=0;i<55;i++) m2[i] += __shfl_down_sync(0xffffffffu, m2[i], off);
    }
    int wid = threadIdx.x>>5;
    if ((threadIdx.x&31)==0){
#pragma unroll
        for (int i=0;i<10;i++) red[wid][i]=m1[i];
#pragma unroll
        for (int i=0;i<55;i++) red[wid][10+i]=m2[i];
    }
    __syncthreads();
    if (threadIdx.x < 65){
        float a=0.f;
#pragma unroll
        for (int w=0;w<8;w++) a += red[w][threadIdx.x];
        if (threadIdx.x < 10) atomicAdd(&g_M1[threadIdx.x], a);
        else atomicAdd(&g_M2[threadIdx.x-10], a);
    }
}

__global__ void k_fold(const float* __restrict__ w1, const float* __restrict__ g1,
                       const float* __restrict__ be1){
    int d = threadIdx.x;
    const double invNK = 1.0/(double)NK;
    double wv[10];
#pragma unroll
    for (int c=0;c<10;c++) wv[c] = (double)w1[c*128+d];
    double m = 0.0;
#pragma unroll
    for (int c=0;c<10;c++) m += ((double)g_M1[c]*invNK)*wv[c];
    double q = 0.0; int t = 0;
#pragma unroll
    for (int a=0;a<10;a++)
#pragma unroll
        for (int b=a;b<10;b++){
            double s2 = (double)g_M2[t++]*invNK;
            double term = s2*wv[a]*wv[b];
            q += (a==b) ? term : 2.0*term;
        }
    double var = q - m*m;
    double a1 = (double)g1[d] / sqrt(var + 1e-5);
    g_c1[d] = (float)((double)be1[d] - m*a1);
#pragma unroll
    for (int c=0;c<10;c++) g_w1p[c*128+d] = (float)(wv[c]*a1);
}

__device__ __forceinline__ float w8row(int r, int c){
    switch(r){
        case 0: return g_w1p[384+c] - g_w1p[768+c];
        case 1: return g_w1p[512+c] - g_w1p[896+c];
        case 2: return g_w1p[640+c] - g_w1p[1024+c];
        case 3: return g_w1p[1152+c];
        case 4: return g_w1p[c]     + g_w1p[768+c];
        case 5: return g_w1p[128+c] + g_w1p[896+c];
        case 6: return g_w1p[256+c] + g_w1p[1024+c];
        default: return g_c1[c];
    }
}

__global__ void __launch_bounds__(NT,1) k_main(
    const float* __restrict__ p, const float* __restrict__ x,
    const float* __restrict__ w2, const float* __restrict__ b2,
    const float* __restrict__ ws, const float* __restrict__ wo,
    const float* __restrict__ bo, float* __restrict__ out)
{
    extern __shared__ float sm[];
    int tid = threadIdx.x, w = tid>>5, lid = tid&31;
    int g = lid>>2, tq = lid&3;
    int wl = w & 7;
    int rA = wl*16;
    bool lowhalf = (w < 8);
    int rg = w & 3, cg = w >> 2;
    int row0 = rg*32;

    // ---- stage fp16 weight fragments ----
    for (int i = tid; i < 1024; i += NT){          // w2
        int lane = i&31, j = (i>>5)&3, K = i>>7;
        int g2 = lane>>2, t2 = lane&3;
        int r0 = K*16 + 2*t2;
        int c0 = (2*j)*8 + g2, c1 = (2*j+1)*8 + g2;
        uint4 v;
        v.x = h2u(__floats2half2_rn(w2[r0*64+c0],     w2[(r0+1)*64+c0]));
        v.y = h2u(__floats2half2_rn(w2[(r0+8)*64+c0], w2[(r0+9)*64+c0]));
        v.z = h2u(__floats2half2_rn(w2[r0*64+c1],     w2[(r0+1)*64+c1]));
        v.w = h2u(__floats2half2_rn(w2[(r0+8)*64+c1], w2[(r0+9)*64+c1]));
        *(uint4*)&sm[F_W2F + i*4] = v;
    }
    for (int i = tid; i < 2048; i += NT){          // ws
        int lane = i&31, j = (i>>5)&7, K = i>>8;
        int g2 = lane>>2, t2 = lane&3;
        int r0 = K*16 + 2*t2;
        int c0 = (2*j)*8 + g2, c1 = (2*j+1)*8 + g2;
        uint4 v;
        v.x = h2u(__floats2half2_rn(ws[r0*128+c0],     ws[(r0+1)*128+c0]));
        v.y = h2u(__floats2half2_rn(ws[(r0+8)*128+c0], ws[(r0+9)*128+c0]));
        v.z = h2u(__floats2half2_rn(ws[r0*128+c1],     ws[(r0+1)*128+c1]));
        v.w = h2u(__floats2half2_rn(ws[(r0+8)*128+c1], ws[(r0+9)*128+c1]));
        *(uint4*)&sm[F_WSF + i*4] = v;
    }
    for (int i = tid; i < 2048; i += NT){          // wo
        int lane = i&31, n = (i>>5)&7, K = i>>8;
        int g2 = lane>>2, t2 = lane&3;
        int r0 = K*16 + 2*t2, c = n*8 + g2;
        uint2 v;
        v.x = h2u(__floats2half2_rn(wo[r0*64+c],     wo[(r0+1)*64+c]));
        v.y = h2u(__floats2half2_rn(wo[(r0+8)*64+c], wo[(r0+9)*64+c]));
        *(uint2*)&sm[F_WOF + i*2] = v;
    }
    if (tid < 256){                                // layer1 B frags (fp16, dup-K)
        int i = tid, l2 = i&31, n2 = i>>5;
        int g2 = l2>>2, t2 = l2&3;
        uint2 v;
#pragma unroll
        for (int par=0; par<2; par++){
            int c = (2*n2+par)*8 + g2;
            __half2 b0 = __floats2half2_rn(w8row(2*t2, c), w8row(2*t2+1, c));
            ((u32*)&v)[par] = h2u(b0);
        }
        *(uint2*)&sm[F_W1F16 + i*2] = v;
    }
    if (tid < 64){ sm[F_B2+tid]=b2[tid]; sm[F_BO+tid]=bo[tid]; sm[F_BNS+tid]=0.f; sm[F_BNQ+tid]=0.f; }
    __syncthreads();

    u32 smb = cvta_sh(sm);
    u32 lmoff = (u32)((lid&15)*272 + ((lid&16)?16:0));
    u32 actW[2], b3[2][2];
    actW[0] = smb + (u32)(F_ACT0*4 + rA*272) + lmoff;
    actW[1] = smb + (u32)(F_ACT1*4 + rA*272) + lmoff;
    b3[0][0] = smb + (u32)(F_ACT0*4 + row0*272) + lmoff;
    b3[0][1] = b3[0][0] + 16*272;
    b3[1][0] = smb + (u32)(F_ACT1*4 + row0*272) + lmoff;
    b3[1][1] = b3[1][0] + 16*272;
    __half* acthb[2] = { (__half*)(sm + F_ACT0), (__half*)(sm + F_ACT1) };

    float bs0=0.f, bs1=0.f, bq0=0.f, bq1=0.f;
    int xrow = wl*16 + (lid>>1);
    int xcol = (lowhalf?0:32) + (lid&1)*16;
    int fbuf = 0;

    for (int t0 = blockIdx.x*2; t0 < NTILES; t0 += gridDim.x*2){
        int tiles[2] = { t0, t0+1 };

        // prefetch x for both tiles -> fp16 pairs
        u32 xh[2][8];
#pragma unroll
        for (int tb=0; tb<2; tb++){
            const float4* xp = (const float4*)(x + ((size_t)tiles[tb]*128 + xrow)*64 + xcol);
#pragma unroll
            for (int i=0;i<4;i++){
                float4 v = xp[i];
                xh[tb][2*i]   = h2u(__floats2half2_rn(v.x, v.y));
                xh[tb][2*i+1] = h2u(__floats2half2_rn(v.z, v.w));
            }
        }

        // ---- GEMM1 both tiles (fp16 2-term split in K) ----
#pragma unroll
        for (int tb=0; tb<2; tb++){
            u32 a0,a1,a2,a3;
            {
                const float* pb = p + (size_t)tiles[tb]*384 + wl*48;
                float cxv=pb[0], cyv=pb[1], czv=pb[2];
                float qa0=pb[3*g],    qa1=pb[3*g+1],  qa2=pb[3*g+2];
                float qb0=pb[3*g+24], qb1=pb[3*g+25], qb2=pb[3*g+26];
                float da0=cxv-qa0, da1=cyv-qa1, da2=czv-qa2;
                float db0=cxv-qb0, db1=cyv-qb1, db2=czv-qb2;
                float dsa=sqrtf(da0*da0+da1*da1+da2*da2);
                float dsb=sqrtf(db0*db0+db1*db1+db2*db2);
                float vA0,vA1,vB0,vB1;
                if (tq==0){ vA0=qa0; vA1=qa1; vB0=qb0; vB1=qb1; }
                else if (tq==1){ vA0=qa2; vA1=dsa; vB0=qb2; vB1=dsb; }
                else if (tq==2){ vA0=cxv; vA1=cyv; vB0=cxv; vB1=cyv; }
                else { vA0=czv; vA1=1.f; vB0=czv; vB1=1.f; }
                __half2 hA = __floats2half2_rn(vA0, vA1);
                float2 fA = __half22float2(hA);
                __half2 lA = __floats2half2_rn(vA0-fA.x, vA1-fA.y);
                __half2 hB = __floats2half2_rn(vB0, vB1);
                float2 fB = __half22float2(hB);
                __half2 lB = __floats2half2_rn(vB0-fB.x, vB1-fB.y);
                a0 = h2u(hA); a1 = h2u(hB); a2 = h2u(lA); a3 = h2u(lB);
            }
            int n2b = lowhalf ? 0 : 4;
#pragma unroll
            for (int j=0;j<4;j++){
                int n2g = n2b + j;
                uint2 bv = *(uint2*)&sm[F_W1F16 + (n2g*32+lid)*2];
                float dA[4] = {0.f,0.f,0.f,0.f};
                float dB[4] = {0.f,0.f,0.f,0.f};
                mma16(dA, a0,a1,a2,a3, bv.x, bv.x);
                mma16(dB, a0,a1,a2,a3, bv.y, bv.y);
                u32 r0 = h2u(__floats2half2_rn(fmaxf(dA[0],0.f), fmaxf(dA[1],0.f)));
                u32 r1 = h2u(__floats2half2_rn(fmaxf(dA[2],0.f), fmaxf(dA[3],0.f)));
                u32 r2 = h2u(__floats2half2_rn(fmaxf(dB[0],0.f), fmaxf(dB[1],0.f)));
                u32 r3 = h2u(__floats2half2_rn(fmaxf(dB[2],0.f), fmaxf(dB[3],0.f)));
                STM4(actW[tb] + (u32)(n2g*32), r0,r1,r2,r3);
            }
        }
        BAR64(wl+1);

        // ---- GEMM2 + px writes both tiles (pair-barrier between read & write) ----
#pragma unroll
        for (int tb=0; tb<2; tb++){
            float d2[4][4];
#pragma unroll
            for (int n=0;n<4;n++){ d2[n][0]=0.f; d2[n][1]=0.f; d2[n][2]=0.f; d2[n][3]=0.f; }
            int n2b = lowhalf ? 0 : 2;
#pragma unroll
            for (int K=0;K<8;K++){
                u32 a0,a1,a2,a3;
                LDM4(a0,a1,a2,a3, actW[tb] + (u32)(K*32));
                float4 bA = *(float4*)&sm[F_W2F + ((K*4+n2b  )*32+lid)*4];
                float4 bB = *(float4*)&sm[F_W2F + ((K*4+n2b+1)*32+lid)*4];
                mma16(d2[0], a0,a1,a2,a3, __float_as_uint(bA.x), __float_as_uint(bA.y));
                mma16(d2[1], a0,a1,a2,a3, __float_as_uint(bA.z), __float_as_uint(bA.w));
                mma16(d2[2], a0,a1,a2,a3, __float_as_uint(bB.x), __float_as_uint(bB.y));
                mma16(d2[3], a0,a1,a2,a3, __float_as_uint(bB.z), __float_as_uint(bB.w));
            }
            // partner warp may still be reading h from this buffer — sync the pair
            BAR64(wl+1);
            int nb = lowhalf ? 0 : 4;
#pragma unroll
            for (int pair=0; pair<2; pair++){
                int n0 = 2*pair, n1 = n0+1;
                int cA = (nb+n0)*8 + 2*tq, cB = (nb+n1)*8 + 2*tq;
                float bAa = sm[F_B2+cA], bAb = sm[F_B2+cA+1];
                float bBa = sm[F_B2+cB], bBb = sm[F_B2+cB+1];
                u32 r0 = h2u(__floats2half2_rn(d2[n0][0]+bAa, d2[n0][1]+bAb));
                u32 r1 = h2u(__floats2half2_rn(d2[n0][2]+bAa, d2[n0][3]+bAb));
                u32 r2 = h2u(__floats2half2_rn(d2[n1][0]+bBa, d2[n1][1]+bBb));
                u32 r3 = h2u(__floats2half2_rn(d2[n1][2]+bBa, d2[n1][3]+bBb));
                STM4(actW[tb] + (u32)(nb*16 + pair*32), r0,r1,r2,r3);
            }
#pragma unroll
            for (int i=0;i<4;i++)
                *(uint2*)(acthb[tb] + xrow*136 + 64 + xcol + i*4) = *(uint2*)&xh[tb][2*i];
        }
        __syncthreads();

        // ---- GEMM3 + softmax both tiles ----
        __half* feath = (__half*)(sm + F_FEAT) + fbuf*2176;
#pragma unroll
        for (int tb=0; tb<2; tb++){
            float d3[2][4][4];
#pragma unroll
            for (int m=0;m<2;m++)
#pragma unroll
                for (int n=0;n<4;n++){ d3[m][n][0]=0.f; d3[m][n][1]=0.f; d3[m][n][2]=0.f; d3[m][n][3]=0.f; }
#pragma unroll
            for (int K=0;K<8;K++){
                u32 a[2][4];
#pragma unroll
                for (int m=0;m<2;m++)
                    LDM4(a[m][0],a[m][1],a[m][2],a[m][3], b3[tb][m] + (u32)(K*32));
                float4 bA = *(float4*)&sm[F_WSF + ((K*8 + 2*cg  )*32+lid)*4];
                float4 bB = *(float4*)&sm[F_WSF + ((K*8 + 2*cg+1)*32+lid)*4];
#pragma unroll
                for (int m=0;m<2;m++){
                    mma16(d3[m][0], a[m][0],a[m][1],a[m][2],a[m][3], __float_as_uint(bA.x), __float_as_uint(bA.y));
                    mma16(d3[m][1], a[m][0],a[m][1],a[m][2],a[m][3], __float_as_uint(bA.z), __float_as_uint(bA.w));
                    mma16(d3[m][2], a[m][0],a[m][1],a[m][2],a[m][3], __float_as_uint(bB.x), __float_as_uint(bB.y));
                    mma16(d3[m][3], a[m][0],a[m][1],a[m][2],a[m][3], __float_as_uint(bB.z), __float_as_uint(bB.w));
                }
            }
            int fbase = tb*8;
#pragma unroll
            for (int m=0;m<2;m++){
                int pt = 2*rg + m;
#pragma unroll
                for (int pb2=0; pb2<2; pb2++){
                    u32 q0,q1,q2,q3;
                    LDM4(q0,q1,q2,q3, b3[tb][m] + (u32)(cg*64 + pb2*32));
#pragma unroll
                    for (int sub=0; sub<2; sub++){
                        int nl = 2*pb2 + sub;
                        int c0 = (4*cg+nl)*8 + 2*tq;
                        u32 ulo = sub? q2 : q0;
                        u32 uhi = sub? q3 : q1;
                        float2 plo = __half22float2(*(__half2*)&ulo);
                        float2 phi = __half22float2(*(__half2*)&uhi);
                        float e0 = __expf(d3[m][nl][0]), e1 = __expf(d3[m][nl][1]);
                        float e2 = __expf(d3[m][nl][2]), e3 = __expf(d3[m][nl][3]);
                        float se = e0+e2, so_ = e1+e3;
                        float ve = fmaf(e0, plo.x, e2*phi.x);
                        float vo = fmaf(e1, plo.y, e3*phi.y);
#pragma unroll
                        for (int mm=4;mm<32;mm<<=1){
                            se += __shfl_xor_sync(0xffffffffu, se, mm);
                            so_ += __shfl_xor_sync(0xffffffffu, so_, mm);
                            ve += __shfl_xor_sync(0xffffffffu, ve, mm);
                            vo += __shfl_xor_sync(0xffffffffu, vo, mm);
                        }
                        if (lid < 4)
                            *(u32*)(feath + (fbase+pt)*136 + c0) =
                                h2u(__floats2half2_rn(__fdividef(ve,se), __fdividef(vo,so_)));
                    }
                }
            }
        }
        __syncthreads();

        // ---- epilogue: 16 FEAT rows @ wo (tile A rows 0-7, tile B rows 8-15) ----
        if (lowhalf){
            u32 fb = smb + (u32)(F_FEAT*4 + fbuf*4352) + lmoff;
            float d[4] = {0.f,0.f,0.f,0.f};
#pragma unroll
            for (int K=0;K<8;K++){
                u32 a0,a1,a2,a3;
                LDM4(a0,a1,a2,a3, fb + (u32)(K*32));
                uint2 bv = *(uint2*)&sm[F_WOF + ((K*8+w)*32+lid)*2];
                mma16(d, a0,a1,a2,a3, bv.x, bv.y);
            }
            int c0 = w*8 + 2*tq;
            float ba = sm[F_BO+c0], bb = sm[F_BO+c0+1];
            float v0 = d[0]+ba, v1 = d[1]+bb;   // FEAT row g   -> tile A point g
            float v2 = d[2]+ba, v3 = d[3]+bb;   // FEAT row g+8 -> tile B point g
            float2 va; va.x=v0; va.y=v1;
            float2 vb; vb.x=v2; vb.y=v3;
            *(float2*)&out[((size_t)tiles[0]*8 + g)*64 + c0] = va;
            *(float2*)&out[((size_t)tiles[1]*8 + g)*64 + c0] = vb;
            bs0 += v0+v2; bq0 += fmaf(v0,v0,v2*v2);
            bs1 += v1+v3; bq1 += fmaf(v1,v1,v3*v3);
        }
        fbuf ^= 1;
    }

    if (lowhalf){
        int c0 = w*8 + 2*tq;
        atomicAdd(&sm[F_BNS+c0  ], bs0);
        atomicAdd(&sm[F_BNS+c0+1], bs1);
        atomicAdd(&sm[F_BNQ+c0  ], bq0);
        atomicAdd(&sm[F_BNQ+c0+1], bq1);
    }
    __syncthreads();
    if (tid < 64){
        atomicAdd(&g_sum2[tid],   sm[F_BNS+tid]);
        atomicAdd(&g_sumsq2[tid], sm[F_BNQ+tid]);
    }
}

__global__ void k_fin(const float* __restrict__ g2, const float* __restrict__ be2){
    int j = threadIdx.x;
    double inv = 1.0/(double)Nn;
    double mu  = (double)g_sum2[j]*inv;
    double var = (double)g_sumsq2[j]*inv - mu*mu;
    double a2  = (double)g2[j] / sqrt(var + 1e-5);
    g_a2[j] = (float)a2;
    g_c2[j] = (float)((double)be2[j] - mu*a2);
}

__global__ void k_norm(float* __restrict__ out){
    __shared__ float a2s[64], c2s[64];
    if (threadIdx.x < 64){ a2s[threadIdx.x]=g_a2[threadIdx.x]; c2s[threadIdx.x]=g_c2[threadIdx.x]; }
    __syncthreads();
    const int nq = Nn*64/4;
    float4* o4 = (float4*)out;
    for (int f = blockIdx.x*blockDim.x + threadIdx.x; f < nq; f += gridDim.x*blockDim.x){
        float4 v = o4[f];
        int j = (f*4) & 63;
        v.x = fmaxf(fmaf(v.x, a2s[j],   c2s[j]),   0.f);
        v.y = fmaxf(fmaf(v.y, a2s[j+1], c2s[j+1]), 0.f);
        v.z = fmaxf(fmaf(v.z, a2s[j+2], c2s[j+2]), 0.f);
        v.w = fmaxf(fmaf(v.w, a2s[j+3], c2s[j+3]), 0.f);
        o4[f] = v;
    }
}

extern "C" void kernel_launch(void* const* d_in, const int* in_sizes, int n_in,
                              void* d_out, int out_size){
    const float* p   = (const float*)d_in[0];
    const float* x   = (const float*)d_in[1];
    const float* w1  = (const float*)d_in[2];
    const float* g1  = (const float*)d_in[4];
    const float* be1 = (const float*)d_in[5];
    const float* w2  = (const float*)d_in[6];
    const float* b2  = (const float*)d_in[7];
    const float* ws  = (const float*)d_in[8];
    const float* wo  = (const float*)d_in[9];
    const float* bo  = (const float*)d_in[10];
    const float* g2  = (const float*)d_in[11];
    const float* be2 = (const float*)d_in[12];
    float* out = (float*)d_out;
    (void)in_sizes; (void)n_in; (void)out_size;

    cudaFuncSetAttribute(k_main, cudaFuncAttributeMaxDynamicSharedMemorySize, SMEM_BYTES);

    k_zero<<<1,64>>>();
    k_stats<<<256,256>>>(p);
    k_fold<<<1,128>>>(w1,g1,be1);
    k_main<<<GRID_MAIN,NT,SMEM_BYTES>>>(p,x,w2,b2,ws,wo,bo,out);
    k_fin<<<1,64>>>(g2,be2);
    k_norm<<<2048,256>>>(out);
}